// round 11
// baseline (speedup 1.0000x reference)
#include <cuda_runtime.h>
#include <cuda_fp16.h>
#include <cstdint>

// Problem constants
#define BB 256
#define SS 64
#define DD 1024
#define HH 16
#define DH 64
#define NREL 15
#define MTOT (BB*SS)   // 16384
#define XELEMS ((size_t)MTOT*DD)

// ---------------------------------------------------------------------------
// Device scratch
// ---------------------------------------------------------------------------
__device__ float g_c[SS*SS];

__device__ __align__(1024) __half g_a [(size_t)MTOT*DD];      // x, then ctx (fp16)
__device__ __align__(1024) __half g_wh[(size_t)4*DD*DD];      // weights fp16

__device__ __align__(1024) __half g_qh[(size_t)MTOT*DD];
__device__ __align__(1024) __half g_ql[(size_t)MTOT*DD];
__device__ __align__(1024) __half g_kh[(size_t)MTOT*DD];
__device__ __align__(1024) __half g_kl[(size_t)MTOT*DD];
__device__ __align__(1024) __half g_vh[(size_t)MTOT*DD];

// pre-swizzled fp16 table tiles
__device__ __align__(16) __half g_ektiles[4096];   // 4 x 16rows x 64 (L128)
__device__ __align__(16) __half g_ectile[2048];    // [evh|pad|evw|pad] 32 x 64 (L128)

// ---------------------------------------------------------------------------
// PTX helpers
// ---------------------------------------------------------------------------
__device__ __forceinline__ uint32_t smem_u32(const void* p) {
    uint32_t a;
    asm("{ .reg .u64 t; cvta.to.shared.u64 t, %1; cvt.u32.u64 %0, t; }" : "=r"(a) : "l"(p));
    return a;
}
__device__ __forceinline__ void cp16(uint32_t dst, const void* src) {
    asm volatile("cp.async.cg.shared.global [%0], [%1], 16;" :: "r"(dst), "l"(src));
}
__device__ __forceinline__ void cp_commit() {
    asm volatile("cp.async.commit_group;" ::: "memory");
}
template<int N> __device__ __forceinline__ void cp_wait() {
    asm volatile("cp.async.wait_group %0;" :: "n"(N) : "memory");
}
__device__ __forceinline__ void ldsm4(uint32_t (&r)[4], uint32_t a) {
    asm volatile("ldmatrix.sync.aligned.m8n8.x4.shared.b16 {%0,%1,%2,%3}, [%4];"
                 : "=r"(r[0]), "=r"(r[1]), "=r"(r[2]), "=r"(r[3]) : "r"(a));
}
__device__ __forceinline__ void ldsm4t(uint32_t (&r)[4], uint32_t a) {
    asm volatile("ldmatrix.sync.aligned.m8n8.x4.trans.shared.b16 {%0,%1,%2,%3}, [%4];"
                 : "=r"(r[0]), "=r"(r[1]), "=r"(r[2]), "=r"(r[3]) : "r"(a));
}
__device__ __forceinline__ void mma16816(float (&c)[4], const uint32_t (&a)[4],
                                         uint32_t b0, uint32_t b1) {
    asm volatile("mma.sync.aligned.m16n8k16.row.col.f32.f16.f16.f32 "
                 "{%0,%1,%2,%3}, {%4,%5,%6,%7}, {%8,%9}, {%0,%1,%2,%3};"
                 : "+f"(c[0]), "+f"(c[1]), "+f"(c[2]), "+f"(c[3])
                 : "r"(a[0]), "r"(a[1]), "r"(a[2]), "r"(a[3]), "r"(b0), "r"(b1));
}

__device__ __forceinline__ uint32_t l128(int r, int c) {
    return (uint32_t)(r * 128 + (((c ^ (r & 7)) & 7) << 4));
}
__device__ __forceinline__ uint32_t l64(int r, int c) {
    return (uint32_t)(r * 64 + (((c ^ (r >> 1)) & 3) << 4));
}

// ---------------------------------------------------------------------------
// prep: c table
// ---------------------------------------------------------------------------
__global__ void prep_kernel(const float* __restrict__ eq_h, const float* __restrict__ eq_w,
                            const float* __restrict__ ek_h, const float* __restrict__ ek_w) {
    int idx = blockIdx.x * 256 + threadIdx.x;
    int i = idx >> 6, j = idx & 63;
    int rr = (i >> 3) - (j >> 3) + 7;
    int rc = (i & 7) - (j & 7) + 7;
    float acc = 0.f;
    #pragma unroll 8
    for (int d = 0; d < 64; ++d) {
        float a = eq_h[rr * 64 + d] + eq_w[rc * 64 + d];
        float b = ek_h[rr * 64 + d] + ek_w[rc * 64 + d];
        acc += a * b;
    }
    g_c[idx] = acc;
}

// Build EK/EC swizzled fp16 tiles. grid 6 x 1024.
__global__ void prep_tiles(const float* __restrict__ ek_h, const float* __restrict__ ek_w,
                           const float* __restrict__ eq_h, const float* __restrict__ eq_w,
                           const float* __restrict__ ev_h, const float* __restrict__ ev_w) {
    int idx = blockIdx.x * 1024 + threadIdx.x;
    if (idx < 4096) {
        int t = idx >> 10, r = (idx >> 6) & 15, d = idx & 63;
        const float* src = (t == 0) ? ek_h : (t == 1) ? ek_w : (t == 2) ? eq_h : eq_w;
        __half v = __float2half((r < 15) ? src[r * 64 + d] : 0.f);
        *(unsigned short*)((char*)g_ektiles + t * 2048 + l128(r, d >> 3) + (d & 7) * 2) =
            *(unsigned short*)&v;
    } else {
        int e = idx - 4096;
        int r = e >> 6, d = e & 63;
        float f = 0.f;
        if (r < 15) f = ev_h[r * 64 + d];
        else if (r >= 16 && r < 31) f = ev_w[(r - 16) * 64 + d];
        __half v = __float2half(f);
        *(unsigned short*)((char*)g_ectile + l128(r, d >> 3) + (d & 7) * 2) =
            *(unsigned short*)&v;
    }
}

// ---------------------------------------------------------------------------
// Fused fp32->fp16 conversion: x + 4 weights, 32 elems/thread
// ---------------------------------------------------------------------------
__global__ __launch_bounds__(256) void conv_all(
    const float* __restrict__ x,
    const float* __restrict__ w0, const float* __restrict__ w1,
    const float* __restrict__ w2, const float* __restrict__ w3,
    __half* __restrict__ da, __half* __restrict__ dw) {
    size_t base = ((size_t)blockIdx.x * 256 + threadIdx.x) * 32;
    const float* src;
    __half* dst;
    size_t off;
    if (base < XELEMS) { src = x; off = base; dst = da + base; }
    else {
        size_t wb = base - XELEMS;
        int which = (int)(wb >> 20);
        src = (which == 0) ? w0 : (which == 1) ? w1 : (which == 2) ? w2 : w3;
        off = wb & 1048575u;
        dst = dw + wb;
    }
    float4 v[8];
    #pragma unroll
    for (int i = 0; i < 8; ++i) v[i] = *(const float4*)(src + off + i * 4);
    #pragma unroll
    for (int i = 0; i < 8; i += 2) {
        __half h[8];
        h[0] = __float2half(v[i].x);   h[1] = __float2half(v[i].y);
        h[2] = __float2half(v[i].z);   h[3] = __float2half(v[i].w);
        h[4] = __float2half(v[i+1].x); h[5] = __float2half(v[i+1].y);
        h[6] = __float2half(v[i+1].z); h[7] = __float2half(v[i+1].w);
        *(uint4*)(dst + i * 4) = *(uint4*)h;
    }
}

// ---------------------------------------------------------------------------
// HMMA fp16 GEMM core v3: acc(128x128) = A(128xK) * W(128xK)^T, K=1024.
// 256 threads, 8 warps (2m x 4n), warp tile 64x32 -> 2 CTAs/SM (decoupled
// barriers). 4-stage ring, 16KB/stage: A @0, B @8192;
// swizzle ((k8 ^ (row>>1)) & 3).
// ---------------------------------------------------------------------------
#define STAGES 4
#define STAGE_BYTES 16384
#define GEMM_SMEM (STAGES * STAGE_BYTES)

__device__ __forceinline__ void gemm_acc(
    const __half* __restrict__ Ap, const __half* __restrict__ Bp,
    int mbase, int nbase, float acc[4][4][4])
{
    extern __shared__ unsigned char sm_raw[];
    uint32_t smbase = smem_u32(sm_raw);
    int tid = threadIdx.x, lane = tid & 31, wid = tid >> 5;
    int wm = (wid >> 2) * 64, wn = (wid & 3) * 32;

    #pragma unroll
    for (int i = 0; i < 4; ++i)
        #pragma unroll
        for (int j = 0; j < 4; ++j)
            #pragma unroll
            for (int e = 0; e < 4; ++e) acc[i][j][e] = 0.f;

    const __half* srcA = Ap + (size_t)mbase * DD;
    const __half* srcB = Bp + (size_t)nbase * DD;

    int lm  = tid >> 1;            // row 0..127
    int lk8 = (tid & 1) * 2;       // first of two 16B chunks
    uint32_t aoff0 = (uint32_t)(lm * 64 + (((lk8)     ^ (lm >> 1)) & 3) * 16);
    uint32_t aoff1 = (uint32_t)(lm * 64 + (((lk8 + 1) ^ (lm >> 1)) & 3) * 16);

    #define LOAD_CHUNK(kc, st) do {                                            \
        uint32_t sb_ = smbase + (st) * STAGE_BYTES;                            \
        size_t gA_ = (size_t)lm * DD + (kc) * 32 + lk8 * 8;                    \
        size_t gB_ = (size_t)lm * DD + (kc) * 32 + lk8 * 8;                    \
        cp16(sb_ + aoff0,        srcA + gA_);                                  \
        cp16(sb_ + aoff1,        srcA + gA_ + 8);                              \
        cp16(sb_ + 8192 + aoff0, srcB + gB_);                                  \
        cp16(sb_ + 8192 + aoff1, srcB + gB_ + 8);                              \
        cp_commit();                                                           \
    } while (0)

    LOAD_CHUNK(0, 0);
    LOAD_CHUNK(1, 1);
    LOAD_CHUNK(2, 2);

    int arow = wm + (lane & 7) + ((lane >> 3) & 1) * 8;
    int brow = wn + (lane & 7) + ((lane >> 3) & 1) * 8;
    int k8l  = (lane >> 4);

    for (int kc = 0; kc < 32; ++kc) {
        cp_wait<2>();
        __syncthreads();
        if (kc + 3 < 32) LOAD_CHUNK(kc + 3, (kc + 3) & 3);
        else             cp_commit();
        uint32_t sb = smbase + (kc & 3) * STAGE_BYTES;

        #pragma unroll
        for (int s16 = 0; s16 < 2; ++s16) {
            int k8 = 2 * s16 + k8l;
            uint32_t av[4][4];
            #pragma unroll
            for (int i = 0; i < 4; ++i) {
                int r = arow + i * 16;
                ldsm4(av[i], sb + (uint32_t)(r * 64 + ((k8 ^ (r >> 1)) & 3) * 16));
            }
            uint32_t bv[2][4];
            #pragma unroll
            for (int jp = 0; jp < 2; ++jp) {
                int r = brow + jp * 16;
                ldsm4(bv[jp], sb + 8192 + (uint32_t)(r * 64 + ((k8 ^ (r >> 1)) & 3) * 16));
            }
            #pragma unroll
            for (int i = 0; i < 4; ++i)
                #pragma unroll
                for (int j = 0; j < 4; ++j)
                    mma16816(acc[i][j], av[i],
                             bv[j >> 1][j & 1], bv[j >> 1][(j & 1) + 2]);
        }
    }
    #undef LOAD_CHUNK
}

// ---------------------------------------------------------------------------
// QKV GEMM: grid (24, 128). nt>>3 selects q/k/v, (nt&7)*128 = n0.
// ---------------------------------------------------------------------------
__global__ __launch_bounds__(256) void qkv_hmma() {
    int nt = blockIdx.x, mt = blockIdx.y;
    int which = nt >> 3, nq = nt & 7;
    float acc[4][4][4];
    gemm_acc(g_a, g_wh + (size_t)which * DD * DD, mt * 128, nq * 128, acc);

    __half* dh = (which == 0) ? g_qh : (which == 1) ? g_kh : g_vh;
    __half* dl = (which == 0) ? g_ql : g_kl;
    int lane = threadIdx.x & 31, wid = threadIdx.x >> 5;
    int wm = (wid >> 2) * 64, wn = (wid & 3) * 32;
    int l4 = lane >> 2, l2 = (lane & 3) * 2;

    #pragma unroll
    for (int i = 0; i < 4; ++i)
        #pragma unroll
        for (int j = 0; j < 4; ++j) {
            int m = mt * 128 + wm + i * 16 + l4;
            int n = nq * 128 + wn + j * 8 + l2;
            int h = n >> 6, d = n & 63;
            int b = m >> 6, s = m & 63;
            size_t i0 = ((size_t)((b * HH + h) * SS + s)) * 64 + d;
            size_t i1 = ((size_t)((b * HH + h) * SS + s + 8)) * 64 + d;
            float v0 = acc[i][j][0], v1 = acc[i][j][1];
            float v2 = acc[i][j][2], v3 = acc[i][j][3];
            __half h0 = __float2half(v0), h1 = __float2half(v1);
            __half h2v = __float2half(v2), h3 = __float2half(v3);
            *(__half2*)(dh + i0) = __halves2half2(h0, h1);
            *(__half2*)(dh + i1) = __halves2half2(h2v, h3);
            if (which < 2) {
                __half l0 = __float2half(v0 - __half2float(h0));
                __half l1 = __float2half(v1 - __half2float(h1));
                __half l2h = __float2half(v2 - __half2float(h2v));
                __half l3 = __float2half(v3 - __half2float(h3));
                *(__half2*)(dl + i0) = __halves2half2(l0, l1);
                *(__half2*)(dl + i1) = __halves2half2(l2h, l3);
            }
        }
}

// ---------------------------------------------------------------------------
// Output GEMM: grid (8, 128)
// ---------------------------------------------------------------------------
__global__ __launch_bounds__(256) void out_hmma(const float* __restrict__ bo,
                                                float* __restrict__ out) {
    int nt = blockIdx.x, mt = blockIdx.y;
    float acc[4][4][4];
    gemm_acc(g_a, g_wh + (size_t)3 * DD * DD, mt * 128, nt * 128, acc);

    int lane = threadIdx.x & 31, wid = threadIdx.x >> 5;
    int wm = (wid >> 2) * 64, wn = (wid & 3) * 32;
    int l4 = lane >> 2, l2 = (lane & 3) * 2;

    #pragma unroll
    for (int i = 0; i < 4; ++i)
        #pragma unroll
        for (int j = 0; j < 4; ++j) {
            int m = mt * 128 + wm + i * 16 + l4;
            int n = nt * 128 + wn + j * 8 + l2;
            float b0 = __ldg(bo + n), b1 = __ldg(bo + n + 1);
            *(float2*)&out[(size_t)m * DD + n] =
                make_float2(acc[i][j][0] + b0, acc[i][j][1] + b1);
            *(float2*)&out[(size_t)(m + 8) * DD + n] =
                make_float2(acc[i][j][2] + b0, acc[i][j][3] + b1);
        }
}

// ---------------------------------------------------------------------------
// MMA attention (exact R8 known-good config: 93KB, 2 CTAs/SM)
// ---------------------------------------------------------------------------
#define AT_Q   0
#define AT_K   8192
#define AT_QL  16384
#define AT_KL  24576
#define AT_V   32768
#define AT_EK  40960
#define AT_EC  49152
#define AT_WW  53248
#define AT_T   57344
#define AT_P   75776
#define AT_PL  83968
#define AT_PM  92160
#define AT_PS  92672
#define AT_BYTES 93184

__global__ __launch_bounds__(256, 2) void attn_mma() {
    extern __shared__ unsigned char am_raw[];
    uint32_t sb = smem_u32(am_raw);
    int tid = threadIdx.x, lane = tid & 31, w = tid >> 5;
    int bx = blockIdx.x;
    int b = bx >> 4, h = bx & 15;
    size_t gbase = (size_t)bx * 4096;

    #pragma unroll
    for (int it = 0; it < 2; ++it) {
        int e = it * 256 + tid;
        int r = e >> 3, c = e & 7;
        uint32_t off = l128(r, c);
        size_t g = gbase + r * 64 + c * 8;
        cp16(sb + AT_Q  + off, g_qh + g);
        cp16(sb + AT_QL + off, g_ql + g);
        cp16(sb + AT_K  + off, g_kh + g);
        cp16(sb + AT_KL + off, g_kl + g);
        cp16(sb + AT_V  + off, g_vh + g);
        cp16(sb + AT_EK + e * 16, (const char*)g_ektiles + e * 16);
        if (it == 0)
            cp16(sb + AT_EC + tid * 16, (const char*)g_ectile + tid * 16);
    }
    cp_commit();
    cp_wait<0>();
    __syncthreads();

    int ms = (w & 3) * 16, ns = (w >> 2) * 32;
    int lrow = (lane & 7) + ((lane >> 3) & 1) * 8;
    int lc   = lane >> 4;
    int l4 = lane >> 2, l2 = lane & 3;

    // ---- Phase 1: S (3-term split) + table mmas ----
    float s[4][4];
    float t0[2][4], t1[2][4];
    #pragma unroll
    for (int j = 0; j < 4; ++j) {
        s[j][0]=s[j][1]=s[j][2]=s[j][3]=0.f;
        if (j < 2) { t0[j][0]=t0[j][1]=t0[j][2]=t0[j][3]=0.f;
                     t1[j][0]=t1[j][1]=t1[j][2]=t1[j][3]=0.f; }
    }
    #pragma unroll
    for (int kk = 0; kk < 4; ++kk) {
        int c = 2 * kk + lc;
        uint32_t ah[4], al[4];
        uint32_t offq = l128(ms + lrow, c);
        ldsm4(ah, sb + AT_Q  + offq);
        ldsm4(al, sb + AT_QL + offq);
        uint32_t bh[2][4], bl[2][4];
        #pragma unroll
        for (int jp = 0; jp < 2; ++jp) {
            uint32_t off = l128(ns + jp * 16 + lrow, c);
            ldsm4(bh[jp], sb + AT_K  + off);
            ldsm4(bl[jp], sb + AT_KL + off);
        }
        #pragma unroll
        for (int j = 0; j < 4; ++j) {
            uint32_t b0h = bh[j >> 1][j & 1], b1h = bh[j >> 1][(j & 1) + 2];
            uint32_t b0l = bl[j >> 1][j & 1], b1l = bl[j >> 1][(j & 1) + 2];
            mma16816(s[j], ah, b0h, b1h);
            mma16816(s[j], ah, b0l, b1l);
            mma16816(s[j], al, b0h, b1h);
        }
        uint32_t ta[4];
        if (w < 4) { ta[0]=ah[0]; ta[1]=ah[1]; ta[2]=ah[2]; ta[3]=ah[3]; }
        else       ldsm4(ta, sb + AT_K + offq);
        uint32_t e0[4], e1[4];
        int tb = (w < 4) ? 0 : 2;
        uint32_t offe = l128(lrow, c);
        ldsm4(e0, sb + AT_EK + tb * 2048 + offe);
        ldsm4(e1, sb + AT_EK + (tb + 1) * 2048 + offe);
        #pragma unroll
        for (int jc = 0; jc < 2; ++jc) {
            mma16816(t0[jc], ta, e0[jc], e0[jc + 2]);
            mma16816(t1[jc], ta, e1[jc], e1[jc + 2]);
        }
    }
    // store table frags (fp32 stride 18)
    {
        unsigned char* tb0 = am_raw + AT_T + ((w < 4) ? 0 : 2 * 4608);
        #pragma unroll
        for (int jc = 0; jc < 2; ++jc) {
            int r0 = jc * 8 + l2 * 2;
            int i0 = ms + l4;
            *(float2*)(tb0 + (size_t)(i0 * 18 + r0) * 4)        = make_float2(t0[jc][0], t0[jc][1]);
            *(float2*)(tb0 + (size_t)((i0 + 8) * 18 + r0) * 4)  = make_float2(t0[jc][2], t0[jc][3]);
            *(float2*)(tb0 + 4608 + (size_t)(i0 * 18 + r0) * 4)       = make_float2(t1[jc][0], t1[jc][1]);
            *(float2*)(tb0 + 4608 + (size_t)((i0 + 8) * 18 + r0) * 4) = make_float2(t1[jc][2], t1[jc][3]);
        }
    }
    __syncthreads();

    // ---- bias in registers ----
    {
        const float* Ah = (const float*)(am_raw + AT_T);
        const float* Aw = Ah + 1152;
        const float* Ch = Aw + 1152;
        const float* Cw = Ch + 1152;
        #pragma unroll
        for (int jc = 0; jc < 4; ++jc)
            #pragma unroll
            for (int q = 0; q < 2; ++q)
                #pragma unroll
                for (int p = 0; p < 2; ++p) {
                    int i = ms + l4 + q * 8;
                    int j = ns + jc * 8 + l2 * 2 + p;
                    int rr = (i >> 3) - (j >> 3) + 7;
                    int rc = (i & 7) - (j & 7) + 7;
                    s[jc][q * 2 + p] = (s[jc][q * 2 + p]
                        + Ah[i * 18 + rr] + Aw[i * 18 + rc]
                        + Ch[j * 18 + rr] + Cw[j * 18 + rc]
                        + __ldg(&g_c[i * 64 + j])) * 0.125f;
                }
    }

    // ---- register softmax ----
    float* pm = (float*)(am_raw + AT_PM);
    float* ps = (float*)(am_raw + AT_PS);
    {
        float m0 = -1e30f, m1 = -1e30f;
        #pragma unroll
        for (int jc = 0; jc < 4; ++jc) {
            m0 = fmaxf(m0, fmaxf(s[jc][0], s[jc][1]));
            m1 = fmaxf(m1, fmaxf(s[jc][2], s[jc][3]));
        }
        m0 = fmaxf(m0, __shfl_xor_sync(0xffffffffu, m0, 1));
        m0 = fmaxf(m0, __shfl_xor_sync(0xffffffffu, m0, 2));
        m1 = fmaxf(m1, __shfl_xor_sync(0xffffffffu, m1, 1));
        m1 = fmaxf(m1, __shfl_xor_sync(0xffffffffu, m1, 2));
        if (l2 == 0) {
            pm[(w >> 2) * 64 + ms + l4]     = m0;
            pm[(w >> 2) * 64 + ms + l4 + 8] = m1;
        }
    }
    __syncthreads();
    float M0 = fmaxf(pm[ms + l4],     pm[64 + ms + l4]);
    float M1 = fmaxf(pm[ms + l4 + 8], pm[64 + ms + l4 + 8]);
    {
        float s0 = 0.f, s1 = 0.f;
        #pragma unroll
        for (int jc = 0; jc < 4; ++jc) {
            s[jc][0] = __expf(s[jc][0] - M0);
            s[jc][1] = __expf(s[jc][1] - M0);
            s[jc][2] = __expf(s[jc][2] - M1);
            s[jc][3] = __expf(s[jc][3] - M1);
            s0 += s[jc][0] + s[jc][1];
            s1 += s[jc][2] + s[jc][3];
        }
        s0 += __shfl_xor_sync(0xffffffffu, s0, 1);
        s0 += __shfl_xor_sync(0xffffffffu, s0, 2);
        s1 += __shfl_xor_sync(0xffffffffu, s1, 1);
        s1 += __shfl_xor_sync(0xffffffffu, s1, 2);
        if (l2 == 0) {
            ps[(w >> 2) * 64 + ms + l4]     = s0;
            ps[(w >> 2) * 64 + ms + l4 + 8] = s1;
        }
    }
    __syncthreads();
    {
        float inv0 = 1.0f / (ps[ms + l4]     + ps[64 + ms + l4]);
        float inv1 = 1.0f / (ps[ms + l4 + 8] + ps[64 + ms + l4 + 8]);
        #pragma unroll
        for (int jc = 0; jc < 4; ++jc)
            #pragma unroll
            for (int q = 0; q < 2; ++q) {
                int row = ms + l4 + q * 8;
                int j0  = ns + jc * 8 + l2 * 2;
                float inv = q ? inv1 : inv0;
                float p0 = s[jc][q * 2] * inv, p1 = s[jc][q * 2 + 1] * inv;
                __half h0 = __float2half(p0), h1 = __float2half(p1);
                __half lo0 = __float2half(p0 - __half2float(h0));
                __half lo1 = __float2half(p1 - __half2float(h1));
                uint32_t off = l128(row, j0 >> 3) + (j0 & 7) * 2;
                *(__half2*)(am_raw + AT_P  + off) = __halves2half2(h0, h1);
                *(__half2*)(am_raw + AT_PL + off) = __halves2half2(lo0, lo1);
            }
    }
    __syncthreads();

    // ---- Wh/Ww masked row sums -> WW tile ----
    {
        int r = tid & 15, it0 = tid >> 4;
        for (int i = it0; i < 64; i += 16) {
            float wh = 0.f, ww = 0.f;
            if (r < 15) {
                int rowj = (i >> 3) - (r - 7);
                if (rowj >= 0 && rowj < 8) {
                    const __half* hp = (const __half*)(am_raw + AT_P  + l128(i, rowj));
                    const __half* lp = (const __half*)(am_raw + AT_PL + l128(i, rowj));
                    #pragma unroll
                    for (int t = 0; t < 8; ++t)
                        wh += __half2float(hp[t]) + __half2float(lp[t]);
                }
                int colj = (i & 7) - (r - 7);
                if (colj >= 0 && colj < 8) {
                    #pragma unroll
                    for (int rj = 0; rj < 8; ++rj) {
                        ww += __half2float(*(const __half*)(am_raw + AT_P  + l128(i, rj) + colj * 2))
                            + __half2float(*(const __half*)(am_raw + AT_PL + l128(i, rj) + colj * 2));
                    }
                }
            }
            __half hwh = __float2half(wh), hww = __float2half(ww);
            int cw = r + 16;
            *(unsigned short*)(am_raw + AT_WW + l64(i, r >> 3)  + (r  & 7) * 2) = *(unsigned short*)&hwh;
            *(unsigned short*)(am_raw + AT_WW + l64(i, cw >> 3) + (cw & 7) * 2) = *(unsigned short*)&hww;
        }
    }
    __syncthreads();

    // ---- ctx: P·V (trans-B) + WW·EC (trans-B) ----
    {
        float o[4][4];
        #pragma unroll
        for (int j = 0; j < 4; ++j) { o[j][0]=o[j][1]=o[j][2]=o[j][3]=0.f; }
        int trow = (lane & 7) + ((lane >> 3) & 1) * 8;
        int tsel = lane >> 4;

        #pragma unroll
        for (int kk = 0; kk < 4; ++kk) {
            int c = 2 * kk + lc;
            uint32_t ph[4], pl[4];
            uint32_t offp = l128(ms + lrow, c);
            ldsm4(ph, sb + AT_P  + offp);
            ldsm4(pl, sb + AT_PL + offp);
            #pragma unroll
            for (int jp = 0; jp < 2; ++jp) {
                uint32_t bv[4];
                ldsm4t(bv, sb + AT_V + l128(kk * 16 + trow, (ns >> 3) + jp * 2 + tsel));
                mma16816(o[jp * 2],     ph, bv[0], bv[1]);
                mma16816(o[jp * 2],     pl, bv[0], bv[1]);
                mma16816(o[jp * 2 + 1], ph, bv[2], bv[3]);
                mma16816(o[jp * 2 + 1], pl, bv[2], bv[3]);
            }
        }
        #pragma unroll
        for (int kk2 = 0; kk2 < 2; ++kk2) {
            uint32_t aw_[4];
            ldsm4(aw_, sb + AT_WW + l64(ms + lrow, 2 * kk2 + lc));
            #pragma unroll
            for (int jp = 0; jp < 2; ++jp) {
                uint32_t ev[4];
                ldsm4t(ev, sb + AT_EC + l128(kk2 * 16 + trow, (ns >> 3) + jp * 2 + tsel));
                mma16816(o[jp * 2],     aw_, ev[0], ev[1]);
                mma16816(o[jp * 2 + 1], aw_, ev[2], ev[3]);
            }
        }
        #pragma unroll
        for (int jc = 0; jc < 4; ++jc) {
            int d = ns + jc * 8 + l2 * 2;
            int i = ms + l4;
            *(__half2*)(g_a + (size_t)(b * 64 + i) * DD + h * 64 + d) =
                __halves2half2(__float2half(o[jc][0]), __float2half(o[jc][1]));
            *(__half2*)(g_a + (size_t)(b * 64 + i + 8) * DD + h * 64 + d) =
                __halves2half2(__float2half(o[jc][2]), __float2half(o[jc][3]));
        }
    }
}

// ---------------------------------------------------------------------------
extern "C" void kernel_launch(void* const* d_in, const int* in_sizes, int n_in,
                              void* d_out, int out_size) {
    const float* x    = (const float*)d_in[0];
    const float* wq   = (const float*)d_in[1];
    const float* wk   = (const float*)d_in[2];
    const float* wv   = (const float*)d_in[3];
    const float* wo   = (const float*)d_in[4];
    const float* bo   = (const float*)d_in[5];
    const float* eq_h = (const float*)d_in[6];
    const float* eq_w = (const float*)d_in[7];
    const float* ek_h = (const float*)d_in[8];
    const float* ek_w = (const float*)d_in[9];
    const float* ev_h = (const float*)d_in[10];
    const float* ev_w = (const float*)d_in[11];
    float* out = (float*)d_out;

    cudaFuncSetAttribute(qkv_hmma, cudaFuncAttributeMaxDynamicSharedMemorySize, GEMM_SMEM);
    cudaFuncSetAttribute(out_hmma, cudaFuncAttributeMaxDynamicSharedMemorySize, GEMM_SMEM);
    cudaFuncSetAttribute(attn_mma, cudaFuncAttributeMaxDynamicSharedMemorySize, AT_BYTES);

    void *p_a = nullptr, *p_wh = nullptr;
    cudaGetSymbolAddress(&p_a,  g_a);
    cudaGetSymbolAddress(&p_wh, g_wh);

    prep_kernel<<<16, 256>>>(eq_h, eq_w, ek_h, ek_w);
    prep_tiles<<<6, 1024>>>(ek_h, ek_w, eq_h, eq_w, ev_h, ev_w);
    conv_all<<<2560, 256>>>(x, wq, wk, wv, wo, (__half*)p_a, (__half*)p_wh);

    qkv_hmma<<<dim3(24, 128), 256, GEMM_SMEM>>>();
    attn_mma<<<BB * HH, 256, AT_BYTES>>>();
    out_hmma<<<dim3(8, 128), 256, GEMM_SMEM>>>(bo, out);
}

// round 12
// speedup vs baseline: 1.0887x; 1.0887x over previous
#include <cuda_runtime.h>
#include <cuda_fp16.h>
#include <cstdint>

// Problem constants
#define BB 256
#define SS 64
#define DD 1024
#define HH 16
#define DH 64
#define NREL 15
#define MTOT (BB*SS)   // 16384
#define XELEMS ((size_t)MTOT*DD)

// ---------------------------------------------------------------------------
// Device scratch
// ---------------------------------------------------------------------------
__device__ float g_c[SS*SS];

__device__ __align__(1024) __half g_a [(size_t)MTOT*DD];      // x, then ctx (fp16)
__device__ __align__(1024) __half g_wh[(size_t)4*DD*DD];      // weights fp16

__device__ __align__(1024) __half g_qh[(size_t)MTOT*DD];
__device__ __align__(1024) __half g_ql[(size_t)MTOT*DD];
__device__ __align__(1024) __half g_kh[(size_t)MTOT*DD];
__device__ __align__(1024) __half g_kl[(size_t)MTOT*DD];
__device__ __align__(1024) __half g_vh[(size_t)MTOT*DD];

// pre-swizzled fp16 table tiles
__device__ __align__(16) __half g_ektiles[4096];   // 4 x 16rows x 64 (L128)
__device__ __align__(16) __half g_ectile[2048];    // [evh|pad|evw|pad] 32 x 64 (L128)

// ---------------------------------------------------------------------------
// PTX helpers
// ---------------------------------------------------------------------------
__device__ __forceinline__ uint32_t smem_u32(const void* p) {
    uint32_t a;
    asm("{ .reg .u64 t; cvta.to.shared.u64 t, %1; cvt.u32.u64 %0, t; }" : "=r"(a) : "l"(p));
    return a;
}
__device__ __forceinline__ void cp16(uint32_t dst, const void* src) {
    asm volatile("cp.async.cg.shared.global [%0], [%1], 16;" :: "r"(dst), "l"(src));
}
__device__ __forceinline__ void cp_commit() {
    asm volatile("cp.async.commit_group;" ::: "memory");
}
template<int N> __device__ __forceinline__ void cp_wait() {
    asm volatile("cp.async.wait_group %0;" :: "n"(N) : "memory");
}
__device__ __forceinline__ void ldsm4(uint32_t (&r)[4], uint32_t a) {
    asm volatile("ldmatrix.sync.aligned.m8n8.x4.shared.b16 {%0,%1,%2,%3}, [%4];"
                 : "=r"(r[0]), "=r"(r[1]), "=r"(r[2]), "=r"(r[3]) : "r"(a));
}
__device__ __forceinline__ void ldsm4t(uint32_t (&r)[4], uint32_t a) {
    asm volatile("ldmatrix.sync.aligned.m8n8.x4.trans.shared.b16 {%0,%1,%2,%3}, [%4];"
                 : "=r"(r[0]), "=r"(r[1]), "=r"(r[2]), "=r"(r[3]) : "r"(a));
}
__device__ __forceinline__ void mma16816(float (&c)[4], const uint32_t (&a)[4],
                                         uint32_t b0, uint32_t b1) {
    asm volatile("mma.sync.aligned.m16n8k16.row.col.f32.f16.f16.f32 "
                 "{%0,%1,%2,%3}, {%4,%5,%6,%7}, {%8,%9}, {%0,%1,%2,%3};"
                 : "+f"(c[0]), "+f"(c[1]), "+f"(c[2]), "+f"(c[3])
                 : "r"(a[0]), "r"(a[1]), "r"(a[2]), "r"(a[3]), "r"(b0), "r"(b1));
}

__device__ __forceinline__ uint32_t l128(int r, int c) {
    return (uint32_t)(r * 128 + (((c ^ (r & 7)) & 7) << 4));
}
__device__ __forceinline__ uint32_t l64(int r, int c) {
    return (uint32_t)(r * 64 + (((c ^ (r >> 1)) & 3) << 4));
}

// ---------------------------------------------------------------------------
// prep: c table
// ---------------------------------------------------------------------------
__global__ void prep_kernel(const float* __restrict__ eq_h, const float* __restrict__ eq_w,
                            const float* __restrict__ ek_h, const float* __restrict__ ek_w) {
    int idx = blockIdx.x * 256 + threadIdx.x;
    int i = idx >> 6, j = idx & 63;
    int rr = (i >> 3) - (j >> 3) + 7;
    int rc = (i & 7) - (j & 7) + 7;
    float acc = 0.f;
    #pragma unroll 8
    for (int d = 0; d < 64; ++d) {
        float a = eq_h[rr * 64 + d] + eq_w[rc * 64 + d];
        float b = ek_h[rr * 64 + d] + ek_w[rc * 64 + d];
        acc += a * b;
    }
    g_c[idx] = acc;
}

// Build EK/EC swizzled fp16 tiles. grid 6 x 1024.
__global__ void prep_tiles(const float* __restrict__ ek_h, const float* __restrict__ ek_w,
                           const float* __restrict__ eq_h, const float* __restrict__ eq_w,
                           const float* __restrict__ ev_h, const float* __restrict__ ev_w) {
    int idx = blockIdx.x * 1024 + threadIdx.x;
    if (idx < 4096) {
        int t = idx >> 10, r = (idx >> 6) & 15, d = idx & 63;
        const float* src = (t == 0) ? ek_h : (t == 1) ? ek_w : (t == 2) ? eq_h : eq_w;
        __half v = __float2half((r < 15) ? src[r * 64 + d] : 0.f);
        *(unsigned short*)((char*)g_ektiles + t * 2048 + l128(r, d >> 3) + (d & 7) * 2) =
            *(unsigned short*)&v;
    } else {
        int e = idx - 4096;
        int r = e >> 6, d = e & 63;
        float f = 0.f;
        if (r < 15) f = ev_h[r * 64 + d];
        else if (r >= 16 && r < 31) f = ev_w[(r - 16) * 64 + d];
        __half v = __float2half(f);
        *(unsigned short*)((char*)g_ectile + l128(r, d >> 3) + (d & 7) * 2) =
            *(unsigned short*)&v;
    }
}

// ---------------------------------------------------------------------------
// Fused fp32->fp16 conversion: x + 4 weights, 32 elems/thread
// ---------------------------------------------------------------------------
__global__ __launch_bounds__(256) void conv_all(
    const float* __restrict__ x,
    const float* __restrict__ w0, const float* __restrict__ w1,
    const float* __restrict__ w2, const float* __restrict__ w3,
    __half* __restrict__ da, __half* __restrict__ dw) {
    size_t base = ((size_t)blockIdx.x * 256 + threadIdx.x) * 32;
    const float* src;
    __half* dst;
    size_t off;
    if (base < XELEMS) { src = x; off = base; dst = da + base; }
    else {
        size_t wb = base - XELEMS;
        int which = (int)(wb >> 20);
        src = (which == 0) ? w0 : (which == 1) ? w1 : (which == 2) ? w2 : w3;
        off = wb & 1048575u;
        dst = dw + wb;
    }
    float4 v[8];
    #pragma unroll
    for (int i = 0; i < 8; ++i) v[i] = *(const float4*)(src + off + i * 4);
    #pragma unroll
    for (int i = 0; i < 8; i += 2) {
        __half h[8];
        h[0] = __float2half(v[i].x);   h[1] = __float2half(v[i].y);
        h[2] = __float2half(v[i].z);   h[3] = __float2half(v[i].w);
        h[4] = __float2half(v[i+1].x); h[5] = __float2half(v[i+1].y);
        h[6] = __float2half(v[i+1].z); h[7] = __float2half(v[i+1].w);
        *(uint4*)(dst + i * 4) = *(uint4*)h;
    }
}

// ---------------------------------------------------------------------------
// HMMA fp16 GEMM core v4: R8 shape (512 thr, 16 warps, 32x32 warp tile) with
// BK=64 -> 16 K-chunks, half the barriers. 4-stage ring, 32KB/stage:
//   A @0 (128 rows x 128B), B @16384 (128 rows x 128B); swizzle (c^(r&7))&7.
// ---------------------------------------------------------------------------
#define STAGES 4
#define STAGE_BYTES 32768
#define GEMM_SMEM (STAGES * STAGE_BYTES)   // 131072

__device__ __forceinline__ void gemm_acc(
    const __half* __restrict__ Ap, const __half* __restrict__ Bp,
    int mbase, int nbase, float acc[2][4][4])
{
    extern __shared__ unsigned char sm_raw[];
    uint32_t smbase = smem_u32(sm_raw);
    int tid = threadIdx.x, lane = tid & 31, wid = tid >> 5;
    int wm = (wid >> 2) * 32, wn = (wid & 3) * 32;

    #pragma unroll
    for (int i = 0; i < 2; ++i)
        #pragma unroll
        for (int j = 0; j < 4; ++j)
            #pragma unroll
            for (int e = 0; e < 4; ++e) acc[i][j][e] = 0.f;

    const __half* srcA = Ap + (size_t)mbase * DD;
    const __half* srcB = Bp + (size_t)nbase * DD;

    int lr  = tid >> 2;            // row 0..127
    int lc0 = (tid & 3) * 2;       // first of two 16B chunks (0,2,4,6)
    uint32_t aoff0 = (uint32_t)(lr * 128 + (((lc0)     ^ (lr & 7)) & 7) * 16);
    uint32_t aoff1 = (uint32_t)(lr * 128 + (((lc0 + 1) ^ (lr & 7)) & 7) * 16);

    #define LOAD_CHUNK(kc, st) do {                                            \
        uint32_t sb_ = smbase + (st) * STAGE_BYTES;                            \
        size_t g_ = (size_t)lr * DD + (kc) * 64 + lc0 * 8;                     \
        cp16(sb_ + aoff0,         srcA + g_);                                  \
        cp16(sb_ + aoff1,         srcA + g_ + 8);                              \
        cp16(sb_ + 16384 + aoff0, srcB + g_);                                  \
        cp16(sb_ + 16384 + aoff1, srcB + g_ + 8);                              \
        cp_commit();                                                           \
    } while (0)

    LOAD_CHUNK(0, 0);
    LOAD_CHUNK(1, 1);
    LOAD_CHUNK(2, 2);

    int arow = wm + (lane & 7) + ((lane >> 3) & 1) * 8;
    int brow = wn + (lane & 7) + ((lane >> 3) & 1) * 8;
    int k8l  = (lane >> 4);   // 0 or 1; actual k8 = 2*s16 + k8l

    for (int kc = 0; kc < 16; ++kc) {
        cp_wait<2>();
        __syncthreads();
        if (kc + 3 < 16) LOAD_CHUNK(kc + 3, (kc + 3) & 3);
        else             cp_commit();
        uint32_t sb = smbase + (kc & 3) * STAGE_BYTES;

        #pragma unroll
        for (int s16 = 0; s16 < 4; ++s16) {
            int k8 = 2 * s16 + k8l;
            uint32_t av[2][4];
            #pragma unroll
            for (int i = 0; i < 2; ++i) {
                int r = arow + i * 16;
                ldsm4(av[i], sb + (uint32_t)(r * 128 + ((k8 ^ (r & 7)) & 7) * 16));
            }
            uint32_t bv[2][4];
            #pragma unroll
            for (int jp = 0; jp < 2; ++jp) {
                int r = brow + jp * 16;
                ldsm4(bv[jp], sb + 16384 + (uint32_t)(r * 128 + ((k8 ^ (r & 7)) & 7) * 16));
            }
            #pragma unroll
            for (int i = 0; i < 2; ++i)
                #pragma unroll
                for (int j = 0; j < 4; ++j)
                    mma16816(acc[i][j], av[i],
                             bv[j >> 1][j & 1], bv[j >> 1][(j & 1) + 2]);
        }
    }
    #undef LOAD_CHUNK
}

// ---------------------------------------------------------------------------
// QKV GEMM: grid (24, 128). nt>>3 selects q/k/v, (nt&7)*128 = n0.
// ---------------------------------------------------------------------------
__global__ __launch_bounds__(512, 1) void qkv_hmma() {
    int nt = blockIdx.x, mt = blockIdx.y;
    int which = nt >> 3, nq = nt & 7;
    float acc[2][4][4];
    gemm_acc(g_a, g_wh + (size_t)which * DD * DD, mt * 128, nq * 128, acc);

    __half* dh = (which == 0) ? g_qh : (which == 1) ? g_kh : g_vh;
    __half* dl = (which == 0) ? g_ql : g_kl;
    int lane = threadIdx.x & 31, wid = threadIdx.x >> 5;
    int wm = (wid >> 2) * 32, wn = (wid & 3) * 32;
    int l4 = lane >> 2, l2 = (lane & 3) * 2;

    #pragma unroll
    for (int i = 0; i < 2; ++i)
        #pragma unroll
        for (int j = 0; j < 4; ++j) {
            int m = mt * 128 + wm + i * 16 + l4;
            int n = nq * 128 + wn + j * 8 + l2;
            int h = n >> 6, d = n & 63;
            int b = m >> 6, s = m & 63;
            size_t i0 = ((size_t)((b * HH + h) * SS + s)) * 64 + d;
            size_t i1 = ((size_t)((b * HH + h) * SS + s + 8)) * 64 + d;
            float v0 = acc[i][j][0], v1 = acc[i][j][1];
            float v2 = acc[i][j][2], v3 = acc[i][j][3];
            __half h0 = __float2half(v0), h1 = __float2half(v1);
            __half h2v = __float2half(v2), h3 = __float2half(v3);
            *(__half2*)(dh + i0) = __halves2half2(h0, h1);
            *(__half2*)(dh + i1) = __halves2half2(h2v, h3);
            if (which < 2) {
                __half l0 = __float2half(v0 - __half2float(h0));
                __half l1 = __float2half(v1 - __half2float(h1));
                __half l2h = __float2half(v2 - __half2float(h2v));
                __half l3 = __float2half(v3 - __half2float(h3));
                *(__half2*)(dl + i0) = __halves2half2(l0, l1);
                *(__half2*)(dl + i1) = __halves2half2(l2h, l3);
            }
        }
}

// ---------------------------------------------------------------------------
// Output GEMM: grid (8, 128)
// ---------------------------------------------------------------------------
__global__ __launch_bounds__(512, 1) void out_hmma(const float* __restrict__ bo,
                                                   float* __restrict__ out) {
    int nt = blockIdx.x, mt = blockIdx.y;
    float acc[2][4][4];
    gemm_acc(g_a, g_wh + (size_t)3 * DD * DD, mt * 128, nt * 128, acc);

    int lane = threadIdx.x & 31, wid = threadIdx.x >> 5;
    int wm = (wid >> 2) * 32, wn = (wid & 3) * 32;
    int l4 = lane >> 2, l2 = (lane & 3) * 2;

    #pragma unroll
    for (int i = 0; i < 2; ++i)
        #pragma unroll
        for (int j = 0; j < 4; ++j) {
            int m = mt * 128 + wm + i * 16 + l4;
            int n = nt * 128 + wn + j * 8 + l2;
            float b0 = __ldg(bo + n), b1 = __ldg(bo + n + 1);
            *(float2*)&out[(size_t)m * DD + n] =
                make_float2(acc[i][j][0] + b0, acc[i][j][1] + b1);
            *(float2*)&out[(size_t)(m + 8) * DD + n] =
                make_float2(acc[i][j][2] + b0, acc[i][j][3] + b1);
        }
}

// ---------------------------------------------------------------------------
// MMA attention (exact R8 known-good config: 93KB, 2 CTAs/SM)
// ---------------------------------------------------------------------------
#define AT_Q   0
#define AT_K   8192
#define AT_QL  16384
#define AT_KL  24576
#define AT_V   32768
#define AT_EK  40960
#define AT_EC  49152
#define AT_WW  53248
#define AT_T   57344
#define AT_P   75776
#define AT_PL  83968
#define AT_PM  92160
#define AT_PS  92672
#define AT_BYTES 93184

__global__ __launch_bounds__(256, 2) void attn_mma() {
    extern __shared__ unsigned char am_raw[];
    uint32_t sb = smem_u32(am_raw);
    int tid = threadIdx.x, lane = tid & 31, w = tid >> 5;
    int bx = blockIdx.x;
    int b = bx >> 4, h = bx & 15;
    size_t gbase = (size_t)bx * 4096;

    #pragma unroll
    for (int it = 0; it < 2; ++it) {
        int e = it * 256 + tid;
        int r = e >> 3, c = e & 7;
        uint32_t off = l128(r, c);
        size_t g = gbase + r * 64 + c * 8;
        cp16(sb + AT_Q  + off, g_qh + g);
        cp16(sb + AT_QL + off, g_ql + g);
        cp16(sb + AT_K  + off, g_kh + g);
        cp16(sb + AT_KL + off, g_kl + g);
        cp16(sb + AT_V  + off, g_vh + g);
        cp16(sb + AT_EK + e * 16, (const char*)g_ektiles + e * 16);
        if (it == 0)
            cp16(sb + AT_EC + tid * 16, (const char*)g_ectile + tid * 16);
    }
    cp_commit();
    cp_wait<0>();
    __syncthreads();

    int ms = (w & 3) * 16, ns = (w >> 2) * 32;
    int lrow = (lane & 7) + ((lane >> 3) & 1) * 8;
    int lc   = lane >> 4;
    int l4 = lane >> 2, l2 = lane & 3;

    // ---- Phase 1: S (3-term split) + table mmas ----
    float s[4][4];
    float t0[2][4], t1[2][4];
    #pragma unroll
    for (int j = 0; j < 4; ++j) {
        s[j][0]=s[j][1]=s[j][2]=s[j][3]=0.f;
        if (j < 2) { t0[j][0]=t0[j][1]=t0[j][2]=t0[j][3]=0.f;
                     t1[j][0]=t1[j][1]=t1[j][2]=t1[j][3]=0.f; }
    }
    #pragma unroll
    for (int kk = 0; kk < 4; ++kk) {
        int c = 2 * kk + lc;
        uint32_t ah[4], al[4];
        uint32_t offq = l128(ms + lrow, c);
        ldsm4(ah, sb + AT_Q  + offq);
        ldsm4(al, sb + AT_QL + offq);
        uint32_t bh[2][4], bl[2][4];
        #pragma unroll
        for (int jp = 0; jp < 2; ++jp) {
            uint32_t off = l128(ns + jp * 16 + lrow, c);
            ldsm4(bh[jp], sb + AT_K  + off);
            ldsm4(bl[jp], sb + AT_KL + off);
        }
        #pragma unroll
        for (int j = 0; j < 4; ++j) {
            uint32_t b0h = bh[j >> 1][j & 1], b1h = bh[j >> 1][(j & 1) + 2];
            uint32_t b0l = bl[j >> 1][j & 1], b1l = bl[j >> 1][(j & 1) + 2];
            mma16816(s[j], ah, b0h, b1h);
            mma16816(s[j], ah, b0l, b1l);
            mma16816(s[j], al, b0h, b1h);
        }
        uint32_t ta[4];
        if (w < 4) { ta[0]=ah[0]; ta[1]=ah[1]; ta[2]=ah[2]; ta[3]=ah[3]; }
        else       ldsm4(ta, sb + AT_K + offq);
        uint32_t e0[4], e1[4];
        int tb = (w < 4) ? 0 : 2;
        uint32_t offe = l128(lrow, c);
        ldsm4(e0, sb + AT_EK + tb * 2048 + offe);
        ldsm4(e1, sb + AT_EK + (tb + 1) * 2048 + offe);
        #pragma unroll
        for (int jc = 0; jc < 2; ++jc) {
            mma16816(t0[jc], ta, e0[jc], e0[jc + 2]);
            mma16816(t1[jc], ta, e1[jc], e1[jc + 2]);
        }
    }
    // store table frags (fp32 stride 18)
    {
        unsigned char* tb0 = am_raw + AT_T + ((w < 4) ? 0 : 2 * 4608);
        #pragma unroll
        for (int jc = 0; jc < 2; ++jc) {
            int r0 = jc * 8 + l2 * 2;
            int i0 = ms + l4;
            *(float2*)(tb0 + (size_t)(i0 * 18 + r0) * 4)        = make_float2(t0[jc][0], t0[jc][1]);
            *(float2*)(tb0 + (size_t)((i0 + 8) * 18 + r0) * 4)  = make_float2(t0[jc][2], t0[jc][3]);
            *(float2*)(tb0 + 4608 + (size_t)(i0 * 18 + r0) * 4)       = make_float2(t1[jc][0], t1[jc][1]);
            *(float2*)(tb0 + 4608 + (size_t)((i0 + 8) * 18 + r0) * 4) = make_float2(t1[jc][2], t1[jc][3]);
        }
    }
    __syncthreads();

    // ---- bias in registers ----
    {
        const float* Ah = (const float*)(am_raw + AT_T);
        const float* Aw = Ah + 1152;
        const float* Ch = Aw + 1152;
        const float* Cw = Ch + 1152;
        #pragma unroll
        for (int jc = 0; jc < 4; ++jc)
            #pragma unroll
            for (int q = 0; q < 2; ++q)
                #pragma unroll
                for (int p = 0; p < 2; ++p) {
                    int i = ms + l4 + q * 8;
                    int j = ns + jc * 8 + l2 * 2 + p;
                    int rr = (i >> 3) - (j >> 3) + 7;
                    int rc = (i & 7) - (j & 7) + 7;
                    s[jc][q * 2 + p] = (s[jc][q * 2 + p]
                        + Ah[i * 18 + rr] + Aw[i * 18 + rc]
                        + Ch[j * 18 + rr] + Cw[j * 18 + rc]
                        + __ldg(&g_c[i * 64 + j])) * 0.125f;
                }
    }

    // ---- register softmax ----
    float* pm = (float*)(am_raw + AT_PM);
    float* ps = (float*)(am_raw + AT_PS);
    {
        float m0 = -1e30f, m1 = -1e30f;
        #pragma unroll
        for (int jc = 0; jc < 4; ++jc) {
            m0 = fmaxf(m0, fmaxf(s[jc][0], s[jc][1]));
            m1 = fmaxf(m1, fmaxf(s[jc][2], s[jc][3]));
        }
        m0 = fmaxf(m0, __shfl_xor_sync(0xffffffffu, m0, 1));
        m0 = fmaxf(m0, __shfl_xor_sync(0xffffffffu, m0, 2));
        m1 = fmaxf(m1, __shfl_xor_sync(0xffffffffu, m1, 1));
        m1 = fmaxf(m1, __shfl_xor_sync(0xffffffffu, m1, 2));
        if (l2 == 0) {
            pm[(w >> 2) * 64 + ms + l4]     = m0;
            pm[(w >> 2) * 64 + ms + l4 + 8] = m1;
        }
    }
    __syncthreads();
    float M0 = fmaxf(pm[ms + l4],     pm[64 + ms + l4]);
    float M1 = fmaxf(pm[ms + l4 + 8], pm[64 + ms + l4 + 8]);
    {
        float s0 = 0.f, s1 = 0.f;
        #pragma unroll
        for (int jc = 0; jc < 4; ++jc) {
            s[jc][0] = __expf(s[jc][0] - M0);
            s[jc][1] = __expf(s[jc][1] - M0);
            s[jc][2] = __expf(s[jc][2] - M1);
            s[jc][3] = __expf(s[jc][3] - M1);
            s0 += s[jc][0] + s[jc][1];
            s1 += s[jc][2] + s[jc][3];
        }
        s0 += __shfl_xor_sync(0xffffffffu, s0, 1);
        s0 += __shfl_xor_sync(0xffffffffu, s0, 2);
        s1 += __shfl_xor_sync(0xffffffffu, s1, 1);
        s1 += __shfl_xor_sync(0xffffffffu, s1, 2);
        if (l2 == 0) {
            ps[(w >> 2) * 64 + ms + l4]     = s0;
            ps[(w >> 2) * 64 + ms + l4 + 8] = s1;
        }
    }
    __syncthreads();
    {
        float inv0 = 1.0f / (ps[ms + l4]     + ps[64 + ms + l4]);
        float inv1 = 1.0f / (ps[ms + l4 + 8] + ps[64 + ms + l4 + 8]);
        #pragma unroll
        for (int jc = 0; jc < 4; ++jc)
            #pragma unroll
            for (int q = 0; q < 2; ++q) {
                int row = ms + l4 + q * 8;
                int j0  = ns + jc * 8 + l2 * 2;
                float inv = q ? inv1 : inv0;
                float p0 = s[jc][q * 2] * inv, p1 = s[jc][q * 2 + 1] * inv;
                __half h0 = __float2half(p0), h1 = __float2half(p1);
                __half lo0 = __float2half(p0 - __half2float(h0));
                __half lo1 = __float2half(p1 - __half2float(h1));
                uint32_t off = l128(row, j0 >> 3) + (j0 & 7) * 2;
                *(__half2*)(am_raw + AT_P  + off) = __halves2half2(h0, h1);
                *(__half2*)(am_raw + AT_PL + off) = __halves2half2(lo0, lo1);
            }
    }
    __syncthreads();

    // ---- Wh/Ww masked row sums -> WW tile ----
    {
        int r = tid & 15, it0 = tid >> 4;
        for (int i = it0; i < 64; i += 16) {
            float wh = 0.f, ww = 0.f;
            if (r < 15) {
                int rowj = (i >> 3) - (r - 7);
                if (rowj >= 0 && rowj < 8) {
                    const __half* hp = (const __half*)(am_raw + AT_P  + l128(i, rowj));
                    const __half* lp = (const __half*)(am_raw + AT_PL + l128(i, rowj));
                    #pragma unroll
                    for (int t = 0; t < 8; ++t)
                        wh += __half2float(hp[t]) + __half2float(lp[t]);
                }
                int colj = (i & 7) - (r - 7);
                if (colj >= 0 && colj < 8) {
                    #pragma unroll
                    for (int rj = 0; rj < 8; ++rj) {
                        ww += __half2float(*(const __half*)(am_raw + AT_P  + l128(i, rj) + colj * 2))
                            + __half2float(*(const __half*)(am_raw + AT_PL + l128(i, rj) + colj * 2));
                    }
                }
            }
            __half hwh = __float2half(wh), hww = __float2half(ww);
            int cw = r + 16;
            *(unsigned short*)(am_raw + AT_WW + l64(i, r >> 3)  + (r  & 7) * 2) = *(unsigned short*)&hwh;
            *(unsigned short*)(am_raw + AT_WW + l64(i, cw >> 3) + (cw & 7) * 2) = *(unsigned short*)&hww;
        }
    }
    __syncthreads();

    // ---- ctx: P·V (trans-B) + WW·EC (trans-B) ----
    {
        float o[4][4];
        #pragma unroll
        for (int j = 0; j < 4; ++j) { o[j][0]=o[j][1]=o[j][2]=o[j][3]=0.f; }
        int trow = (lane & 7) + ((lane >> 3) & 1) * 8;
        int tsel = lane >> 4;

        #pragma unroll
        for (int kk = 0; kk < 4; ++kk) {
            int c = 2 * kk + lc;
            uint32_t ph[4], pl[4];
            uint32_t offp = l128(ms + lrow, c);
            ldsm4(ph, sb + AT_P  + offp);
            ldsm4(pl, sb + AT_PL + offp);
            #pragma unroll
            for (int jp = 0; jp < 2; ++jp) {
                uint32_t bv[4];
                ldsm4t(bv, sb + AT_V + l128(kk * 16 + trow, (ns >> 3) + jp * 2 + tsel));
                mma16816(o[jp * 2],     ph, bv[0], bv[1]);
                mma16816(o[jp * 2],     pl, bv[0], bv[1]);
                mma16816(o[jp * 2 + 1], ph, bv[2], bv[3]);
                mma16816(o[jp * 2 + 1], pl, bv[2], bv[3]);
            }
        }
        #pragma unroll
        for (int kk2 = 0; kk2 < 2; ++kk2) {
            uint32_t aw_[4];
            ldsm4(aw_, sb + AT_WW + l64(ms + lrow, 2 * kk2 + lc));
            #pragma unroll
            for (int jp = 0; jp < 2; ++jp) {
                uint32_t ev[4];
                ldsm4t(ev, sb + AT_EC + l128(kk2 * 16 + trow, (ns >> 3) + jp * 2 + tsel));
                mma16816(o[jp * 2],     aw_, ev[0], ev[1]);
                mma16816(o[jp * 2 + 1], aw_, ev[2], ev[3]);
            }
        }
        #pragma unroll
        for (int jc = 0; jc < 4; ++jc) {
            int d = ns + jc * 8 + l2 * 2;
            int i = ms + l4;
            *(__half2*)(g_a + (size_t)(b * 64 + i) * DD + h * 64 + d) =
                __halves2half2(__float2half(o[jc][0]), __float2half(o[jc][1]));
            *(__half2*)(g_a + (size_t)(b * 64 + i + 8) * DD + h * 64 + d) =
                __halves2half2(__float2half(o[jc][2]), __float2half(o[jc][3]));
        }
    }
}

// ---------------------------------------------------------------------------
extern "C" void kernel_launch(void* const* d_in, const int* in_sizes, int n_in,
                              void* d_out, int out_size) {
    const float* x    = (const float*)d_in[0];
    const float* wq   = (const float*)d_in[1];
    const float* wk   = (const float*)d_in[2];
    const float* wv   = (const float*)d_in[3];
    const float* wo   = (const float*)d_in[4];
    const float* bo   = (const float*)d_in[5];
    const float* eq_h = (const float*)d_in[6];
    const float* eq_w = (const float*)d_in[7];
    const float* ek_h = (const float*)d_in[8];
    const float* ek_w = (const float*)d_in[9];
    const float* ev_h = (const float*)d_in[10];
    const float* ev_w = (const float*)d_in[11];
    float* out = (float*)d_out;

    cudaFuncSetAttribute(qkv_hmma, cudaFuncAttributeMaxDynamicSharedMemorySize, GEMM_SMEM);
    cudaFuncSetAttribute(out_hmma, cudaFuncAttributeMaxDynamicSharedMemorySize, GEMM_SMEM);
    cudaFuncSetAttribute(attn_mma, cudaFuncAttributeMaxDynamicSharedMemorySize, AT_BYTES);

    void *p_a = nullptr, *p_wh = nullptr;
    cudaGetSymbolAddress(&p_a,  g_a);
    cudaGetSymbolAddress(&p_wh, g_wh);

    prep_kernel<<<16, 256>>>(eq_h, eq_w, ek_h, ek_w);
    prep_tiles<<<6, 1024>>>(ek_h, ek_w, eq_h, eq_w, ev_h, ev_w);
    conv_all<<<2560, 256>>>(x, wq, wk, wv, wo, (__half*)p_a, (__half*)p_wh);

    qkv_hmma<<<dim3(24, 128), 512, GEMM_SMEM>>>();
    attn_mma<<<BB * HH, 256, AT_BYTES>>>();
    out_hmma<<<dim3(8, 128), 512, GEMM_SMEM>>>(bo, out);
}

// round 13
// speedup vs baseline: 1.1549x; 1.0608x over previous
#include <cuda_runtime.h>
#include <cuda_fp16.h>
#include <cstdint>

// Problem constants
#define BB 256
#define SS 64
#define DD 1024
#define HH 16
#define DH 64
#define NREL 15
#define MTOT (BB*SS)   // 16384
#define XELEMS ((size_t)MTOT*DD)

// ---------------------------------------------------------------------------
// Device scratch
// ---------------------------------------------------------------------------
__device__ float g_c[SS*SS];

__device__ __align__(1024) __half g_a [(size_t)MTOT*DD];      // x, then ctx (fp16)
__device__ __align__(1024) __half g_wh[(size_t)4*DD*DD];      // weights fp16

__device__ __align__(1024) __half g_qh[(size_t)MTOT*DD];
__device__ __align__(1024) __half g_ql[(size_t)MTOT*DD];
__device__ __align__(1024) __half g_kh[(size_t)MTOT*DD];
__device__ __align__(1024) __half g_kl[(size_t)MTOT*DD];
__device__ __align__(1024) __half g_vh[(size_t)MTOT*DD];

// pre-swizzled fp16 table tiles
__device__ __align__(16) __half g_ektiles[4096];   // 4 x 16rows x 64 (L128)
__device__ __align__(16) __half g_ectile[2048];    // [evh|pad|evw|pad] 32 x 64 (L128)

// ---------------------------------------------------------------------------
// PTX helpers
// ---------------------------------------------------------------------------
__device__ __forceinline__ uint32_t smem_u32(const void* p) {
    uint32_t a;
    asm("{ .reg .u64 t; cvta.to.shared.u64 t, %1; cvt.u32.u64 %0, t; }" : "=r"(a) : "l"(p));
    return a;
}
__device__ __forceinline__ void cp16(uint32_t dst, const void* src) {
    asm volatile("cp.async.cg.shared.global [%0], [%1], 16;" :: "r"(dst), "l"(src));
}
__device__ __forceinline__ void cp_commit() {
    asm volatile("cp.async.commit_group;" ::: "memory");
}
template<int N> __device__ __forceinline__ void cp_wait() {
    asm volatile("cp.async.wait_group %0;" :: "n"(N) : "memory");
}
__device__ __forceinline__ void ldsm4(uint32_t (&r)[4], uint32_t a) {
    asm volatile("ldmatrix.sync.aligned.m8n8.x4.shared.b16 {%0,%1,%2,%3}, [%4];"
                 : "=r"(r[0]), "=r"(r[1]), "=r"(r[2]), "=r"(r[3]) : "r"(a));
}
__device__ __forceinline__ void ldsm4t(uint32_t (&r)[4], uint32_t a) {
    asm volatile("ldmatrix.sync.aligned.m8n8.x4.trans.shared.b16 {%0,%1,%2,%3}, [%4];"
                 : "=r"(r[0]), "=r"(r[1]), "=r"(r[2]), "=r"(r[3]) : "r"(a));
}
__device__ __forceinline__ void mma16816(float (&c)[4], const uint32_t (&a)[4],
                                         uint32_t b0, uint32_t b1) {
    asm volatile("mma.sync.aligned.m16n8k16.row.col.f32.f16.f16.f32 "
                 "{%0,%1,%2,%3}, {%4,%5,%6,%7}, {%8,%9}, {%0,%1,%2,%3};"
                 : "+f"(c[0]), "+f"(c[1]), "+f"(c[2]), "+f"(c[3])
                 : "r"(a[0]), "r"(a[1]), "r"(a[2]), "r"(a[3]), "r"(b0), "r"(b1));
}

__device__ __forceinline__ uint32_t l128(int r, int c) {
    return (uint32_t)(r * 128 + (((c ^ (r & 7)) & 7) << 4));
}
__device__ __forceinline__ uint32_t l64(int r, int c) {
    return (uint32_t)(r * 64 + (((c ^ (r >> 1)) & 3) << 4));
}

// ---------------------------------------------------------------------------
// mega_prep: one launch does everything upstream of qkv_hmma.
//   blocks [0, 4096)      : x fp32->fp16, 16 elems/thread
//   blocks [4096, 6144)   : weights fp32->fp16, 8 elems/thread
//   blocks [6144, 6160)   : g_c table (prep_kernel)
//   blocks [6160, 6184)   : EK/EC swizzled tiles (prep_tiles)
// ---------------------------------------------------------------------------
__global__ __launch_bounds__(256) void mega_prep(
    const float* __restrict__ x,
    const float* __restrict__ w0, const float* __restrict__ w1,
    const float* __restrict__ w2, const float* __restrict__ w3,
    const float* __restrict__ eq_h, const float* __restrict__ eq_w,
    const float* __restrict__ ek_h, const float* __restrict__ ek_w,
    const float* __restrict__ ev_h, const float* __restrict__ ev_w)
{
    int bid = blockIdx.x;
    int tid = threadIdx.x;

    if (bid < 4096) {
        // x conversion: 16 elems/thread
        size_t base = ((size_t)bid * 256 + tid) * 16;
        #pragma unroll
        for (int half8 = 0; half8 < 2; ++half8) {
            size_t bb = base + half8 * 8;
            float4 a = *(const float4*)(x + bb);
            float4 c = *(const float4*)(x + bb + 4);
            float v[8] = {a.x, a.y, a.z, a.w, c.x, c.y, c.z, c.w};
            __half h[8];
            #pragma unroll
            for (int i = 0; i < 8; ++i) h[i] = __float2half(v[i]);
            *(uint4*)(g_a + bb) = *(uint4*)h;
        }
    } else if (bid < 6144) {
        // weight conversion: 8 elems/thread
        int blk = bid - 4096;
        int which = blk >> 9;
        const float* src = (which == 0) ? w0 : (which == 1) ? w1 : (which == 2) ? w2 : w3;
        size_t lbase = ((size_t)(blk & 511) * 256 + tid) * 8;
        float4 a = *(const float4*)(src + lbase);
        float4 c = *(const float4*)(src + lbase + 4);
        float v[8] = {a.x, a.y, a.z, a.w, c.x, c.y, c.z, c.w};
        __half h[8];
        #pragma unroll
        for (int i = 0; i < 8; ++i) h[i] = __float2half(v[i]);
        *(uint4*)(g_wh + (size_t)which * DD * DD + lbase) = *(uint4*)h;
    } else if (bid < 6160) {
        // g_c table
        int idx = (bid - 6144) * 256 + tid;
        int i = idx >> 6, j = idx & 63;
        int rr = (i >> 3) - (j >> 3) + 7;
        int rc = (i & 7) - (j & 7) + 7;
        float acc = 0.f;
        #pragma unroll 8
        for (int d = 0; d < 64; ++d) {
            float a = eq_h[rr * 64 + d] + eq_w[rc * 64 + d];
            float b = ek_h[rr * 64 + d] + ek_w[rc * 64 + d];
            acc += a * b;
        }
        g_c[idx] = acc;
    } else {
        // EK/EC swizzled tiles: 24 blocks x 256 threads = 6144 slots
        int idx = (bid - 6160) * 256 + tid;
        if (idx < 4096) {
            int t = idx >> 10, r = (idx >> 6) & 15, d = idx & 63;
            const float* src = (t == 0) ? ek_h : (t == 1) ? ek_w : (t == 2) ? eq_h : eq_w;
            __half v = __float2half((r < 15) ? src[r * 64 + d] : 0.f);
            *(unsigned short*)((char*)g_ektiles + t * 2048 + l128(r, d >> 3) + (d & 7) * 2) =
                *(unsigned short*)&v;
        } else {
            int e = idx - 4096;
            int r = e >> 6, d = e & 63;
            float f = 0.f;
            if (r < 15) f = ev_h[r * 64 + d];
            else if (r >= 16 && r < 31) f = ev_w[(r - 16) * 64 + d];
            __half v = __float2half(f);
            *(unsigned short*)((char*)g_ectile + l128(r, d >> 3) + (d & 7) * 2) =
                *(unsigned short*)&v;
        }
    }
}

// ---------------------------------------------------------------------------
// HMMA fp16 GEMM core (exact R8): acc(128x128) = A * W^T, K=1024.
// 512 threads, 16 warps (4x4), warp tile 32x32. 4-stage ring, 16KB/stage.
// ---------------------------------------------------------------------------
#define STAGES 4
#define STAGE_BYTES 16384
#define GEMM_SMEM (STAGES * STAGE_BYTES)

__device__ __forceinline__ void gemm_acc(
    const __half* __restrict__ Ap, const __half* __restrict__ Bp,
    int mbase, int nbase, float acc[2][4][4])
{
    extern __shared__ unsigned char sm_raw[];
    uint32_t smbase = smem_u32(sm_raw);
    int tid = threadIdx.x, lane = tid & 31, wid = tid >> 5;
    int wm = (wid >> 2) * 32, wn = (wid & 3) * 32;

    #pragma unroll
    for (int i = 0; i < 2; ++i)
        #pragma unroll
        for (int j = 0; j < 4; ++j)
            #pragma unroll
            for (int e = 0; e < 4; ++e) acc[i][j][e] = 0.f;

    const __half* srcA = Ap + (size_t)mbase * DD;
    const __half* srcB = Bp + (size_t)nbase * DD;

    int lm  = tid >> 2;
    int lk8 = tid & 3;
    uint32_t loff = (uint32_t)(lm * 64 + ((lk8 ^ (lm >> 1)) & 3) * 16);

    #define LOAD_CHUNK(kc, st) do {                                            \
        uint32_t sb_ = smbase + (st) * STAGE_BYTES;                            \
        size_t g_ = (size_t)lm * DD + (kc) * 32 + lk8 * 8;                     \
        cp16(sb_ + loff,        srcA + g_);                                    \
        cp16(sb_ + 8192 + loff, srcB + g_);                                    \
        cp_commit();                                                           \
    } while (0)

    LOAD_CHUNK(0, 0);
    LOAD_CHUNK(1, 1);
    LOAD_CHUNK(2, 2);

    int arow = wm + (lane & 7) + ((lane >> 3) & 1) * 8;
    int brow = wn + (lane & 7) + ((lane >> 3) & 1) * 8;
    int k8l  = (lane >> 4);

    for (int kc = 0; kc < 32; ++kc) {
        cp_wait<2>();
        __syncthreads();
        if (kc + 3 < 32) LOAD_CHUNK(kc + 3, (kc + 3) & 3);
        else             cp_commit();
        uint32_t sb = smbase + (kc & 3) * STAGE_BYTES;

        #pragma unroll
        for (int s16 = 0; s16 < 2; ++s16) {
            int k8 = 2 * s16 + k8l;
            uint32_t av[2][4];
            #pragma unroll
            for (int i = 0; i < 2; ++i) {
                int r = arow + i * 16;
                uint32_t ad = sb + (uint32_t)(r * 64 + ((k8 ^ (r >> 1)) & 3) * 16);
                ldsm4(av[i], ad);
            }
            uint32_t bv[2][4];
            #pragma unroll
            for (int jp = 0; jp < 2; ++jp) {
                int r = brow + jp * 16;
                uint32_t ad = sb + 8192 + (uint32_t)(r * 64 + ((k8 ^ (r >> 1)) & 3) * 16);
                ldsm4(bv[jp], ad);
            }
            #pragma unroll
            for (int i = 0; i < 2; ++i)
                #pragma unroll
                for (int j = 0; j < 4; ++j)
                    mma16816(acc[i][j], av[i],
                             bv[j >> 1][j & 1], bv[j >> 1][(j & 1) + 2]);
        }
    }
    #undef LOAD_CHUNK
}

// ---------------------------------------------------------------------------
// QKV GEMM: epilogue writes fp16 q/k (hi+lo) and v into (B,H,S,DH)
// ---------------------------------------------------------------------------
__global__ __launch_bounds__(512, 1) void qkv_hmma() {
    int nt = blockIdx.x, mt = blockIdx.y;
    int which = nt >> 3, nq = nt & 7;
    float acc[2][4][4];
    gemm_acc(g_a, g_wh + (size_t)which * DD * DD, mt * 128, nq * 128, acc);

    __half* dh = (which == 0) ? g_qh : (which == 1) ? g_kh : g_vh;
    __half* dl = (which == 0) ? g_ql : g_kl;
    int lane = threadIdx.x & 31, wid = threadIdx.x >> 5;
    int wm = (wid >> 2) * 32, wn = (wid & 3) * 32;
    int l4 = lane >> 2, l2 = (lane & 3) * 2;

    #pragma unroll
    for (int i = 0; i < 2; ++i)
        #pragma unroll
        for (int j = 0; j < 4; ++j) {
            int m = mt * 128 + wm + i * 16 + l4;
            int n = nq * 128 + wn + j * 8 + l2;
            int h = n >> 6, d = n & 63;
            int b = m >> 6, s = m & 63;
            size_t i0 = ((size_t)((b * HH + h) * SS + s)) * 64 + d;
            size_t i1 = ((size_t)((b * HH + h) * SS + s + 8)) * 64 + d;
            float v0 = acc[i][j][0], v1 = acc[i][j][1];
            float v2 = acc[i][j][2], v3 = acc[i][j][3];
            __half h0 = __float2half(v0), h1 = __float2half(v1);
            __half h2v = __float2half(v2), h3 = __float2half(v3);
            *(__half2*)(dh + i0) = __halves2half2(h0, h1);
            *(__half2*)(dh + i1) = __halves2half2(h2v, h3);
            if (which < 2) {
                __half l0 = __float2half(v0 - __half2float(h0));
                __half l1 = __float2half(v1 - __half2float(h1));
                __half l2h = __float2half(v2 - __half2float(h2v));
                __half l3 = __float2half(v3 - __half2float(h3));
                *(__half2*)(dl + i0) = __halves2half2(l0, l1);
                *(__half2*)(dl + i1) = __halves2half2(l2h, l3);
            }
        }
}

// ---------------------------------------------------------------------------
// Output GEMM: out = ctx @ wo^T + bo
// ---------------------------------------------------------------------------
__global__ __launch_bounds__(512, 1) void out_hmma(const float* __restrict__ bo,
                                                   float* __restrict__ out) {
    int nt = blockIdx.x, mt = blockIdx.y;
    float acc[2][4][4];
    gemm_acc(g_a, g_wh + (size_t)3 * DD * DD, mt * 128, nt * 128, acc);

    int lane = threadIdx.x & 31, wid = threadIdx.x >> 5;
    int wm = (wid >> 2) * 32, wn = (wid & 3) * 32;
    int l4 = lane >> 2, l2 = (lane & 3) * 2;

    #pragma unroll
    for (int i = 0; i < 2; ++i)
        #pragma unroll
        for (int j = 0; j < 4; ++j) {
            int m = mt * 128 + wm + i * 16 + l4;
            int n = nt * 128 + wn + j * 8 + l2;
            float b0 = __ldg(bo + n), b1 = __ldg(bo + n + 1);
            *(float2*)&out[(size_t)m * DD + n] =
                make_float2(acc[i][j][0] + b0, acc[i][j][1] + b1);
            *(float2*)&out[(size_t)(m + 8) * DD + n] =
                make_float2(acc[i][j][2] + b0, acc[i][j][3] + b1);
        }
}

// ---------------------------------------------------------------------------
// MMA attention (exact R8 known-good config: 93KB, 2 CTAs/SM)
// ---------------------------------------------------------------------------
#define AT_Q   0
#define AT_K   8192
#define AT_QL  16384
#define AT_KL  24576
#define AT_V   32768
#define AT_EK  40960
#define AT_EC  49152
#define AT_WW  53248
#define AT_T   57344
#define AT_P   75776
#define AT_PL  83968
#define AT_PM  92160
#define AT_PS  92672
#define AT_BYTES 93184

__global__ __launch_bounds__(256, 2) void attn_mma() {
    extern __shared__ unsigned char am_raw[];
    uint32_t sb = smem_u32(am_raw);
    int tid = threadIdx.x, lane = tid & 31, w = tid >> 5;
    int bx = blockIdx.x;
    int b = bx >> 4, h = bx & 15;
    size_t gbase = (size_t)bx * 4096;

    #pragma unroll
    for (int it = 0; it < 2; ++it) {
        int e = it * 256 + tid;
        int r = e >> 3, c = e & 7;
        uint32_t off = l128(r, c);
        size_t g = gbase + r * 64 + c * 8;
        cp16(sb + AT_Q  + off, g_qh + g);
        cp16(sb + AT_QL + off, g_ql + g);
        cp16(sb + AT_K  + off, g_kh + g);
        cp16(sb + AT_KL + off, g_kl + g);
        cp16(sb + AT_V  + off, g_vh + g);
        cp16(sb + AT_EK + e * 16, (const char*)g_ektiles + e * 16);
        if (it == 0)
            cp16(sb + AT_EC + tid * 16, (const char*)g_ectile + tid * 16);
    }
    cp_commit();
    cp_wait<0>();
    __syncthreads();

    int ms = (w & 3) * 16, ns = (w >> 2) * 32;
    int lrow = (lane & 7) + ((lane >> 3) & 1) * 8;
    int lc   = lane >> 4;
    int l4 = lane >> 2, l2 = lane & 3;

    // ---- Phase 1: S (3-term split) + table mmas ----
    float s[4][4];
    float t0[2][4], t1[2][4];
    #pragma unroll
    for (int j = 0; j < 4; ++j) {
        s[j][0]=s[j][1]=s[j][2]=s[j][3]=0.f;
        if (j < 2) { t0[j][0]=t0[j][1]=t0[j][2]=t0[j][3]=0.f;
                     t1[j][0]=t1[j][1]=t1[j][2]=t1[j][3]=0.f; }
    }
    #pragma unroll
    for (int kk = 0; kk < 4; ++kk) {
        int c = 2 * kk + lc;
        uint32_t ah[4], al[4];
        uint32_t offq = l128(ms + lrow, c);
        ldsm4(ah, sb + AT_Q  + offq);
        ldsm4(al, sb + AT_QL + offq);
        uint32_t bh[2][4], bl[2][4];
        #pragma unroll
        for (int jp = 0; jp < 2; ++jp) {
            uint32_t off = l128(ns + jp * 16 + lrow, c);
            ldsm4(bh[jp], sb + AT_K  + off);
            ldsm4(bl[jp], sb + AT_KL + off);
        }
        #pragma unroll
        for (int j = 0; j < 4; ++j) {
            uint32_t b0h = bh[j >> 1][j & 1], b1h = bh[j >> 1][(j & 1) + 2];
            uint32_t b0l = bl[j >> 1][j & 1], b1l = bl[j >> 1][(j & 1) + 2];
            mma16816(s[j], ah, b0h, b1h);
            mma16816(s[j], ah, b0l, b1l);
            mma16816(s[j], al, b0h, b1h);
        }
        uint32_t ta[4];
        if (w < 4) { ta[0]=ah[0]; ta[1]=ah[1]; ta[2]=ah[2]; ta[3]=ah[3]; }
        else       ldsm4(ta, sb + AT_K + offq);
        uint32_t e0[4], e1[4];
        int tb = (w < 4) ? 0 : 2;
        uint32_t offe = l128(lrow, c);
        ldsm4(e0, sb + AT_EK + tb * 2048 + offe);
        ldsm4(e1, sb + AT_EK + (tb + 1) * 2048 + offe);
        #pragma unroll
        for (int jc = 0; jc < 2; ++jc) {
            mma16816(t0[jc], ta, e0[jc], e0[jc + 2]);
            mma16816(t1[jc], ta, e1[jc], e1[jc + 2]);
        }
    }
    // store table frags (fp32 stride 18)
    {
        unsigned char* tb0 = am_raw + AT_T + ((w < 4) ? 0 : 2 * 4608);
        #pragma unroll
        for (int jc = 0; jc < 2; ++jc) {
            int r0 = jc * 8 + l2 * 2;
            int i0 = ms + l4;
            *(float2*)(tb0 + (size_t)(i0 * 18 + r0) * 4)        = make_float2(t0[jc][0], t0[jc][1]);
            *(float2*)(tb0 + (size_t)((i0 + 8) * 18 + r0) * 4)  = make_float2(t0[jc][2], t0[jc][3]);
            *(float2*)(tb0 + 4608 + (size_t)(i0 * 18 + r0) * 4)       = make_float2(t1[jc][0], t1[jc][1]);
            *(float2*)(tb0 + 4608 + (size_t)((i0 + 8) * 18 + r0) * 4) = make_float2(t1[jc][2], t1[jc][3]);
        }
    }
    __syncthreads();

    // ---- bias in registers ----
    {
        const float* Ah = (const float*)(am_raw + AT_T);
        const float* Aw = Ah + 1152;
        const float* Ch = Aw + 1152;
        const float* Cw = Ch + 1152;
        #pragma unroll
        for (int jc = 0; jc < 4; ++jc)
            #pragma unroll
            for (int q = 0; q < 2; ++q)
                #pragma unroll
                for (int p = 0; p < 2; ++p) {
                    int i = ms + l4 + q * 8;
                    int j = ns + jc * 8 + l2 * 2 + p;
                    int rr = (i >> 3) - (j >> 3) + 7;
                    int rc = (i & 7) - (j & 7) + 7;
                    s[jc][q * 2 + p] = (s[jc][q * 2 + p]
                        + Ah[i * 18 + rr] + Aw[i * 18 + rc]
                        + Ch[j * 18 + rr] + Cw[j * 18 + rc]
                        + __ldg(&g_c[i * 64 + j])) * 0.125f;
                }
    }

    // ---- register softmax ----
    float* pm = (float*)(am_raw + AT_PM);
    float* ps = (float*)(am_raw + AT_PS);
    {
        float m0 = -1e30f, m1 = -1e30f;
        #pragma unroll
        for (int jc = 0; jc < 4; ++jc) {
            m0 = fmaxf(m0, fmaxf(s[jc][0], s[jc][1]));
            m1 = fmaxf(m1, fmaxf(s[jc][2], s[jc][3]));
        }
        m0 = fmaxf(m0, __shfl_xor_sync(0xffffffffu, m0, 1));
        m0 = fmaxf(m0, __shfl_xor_sync(0xffffffffu, m0, 2));
        m1 = fmaxf(m1, __shfl_xor_sync(0xffffffffu, m1, 1));
        m1 = fmaxf(m1, __shfl_xor_sync(0xffffffffu, m1, 2));
        if (l2 == 0) {
            pm[(w >> 2) * 64 + ms + l4]     = m0;
            pm[(w >> 2) * 64 + ms + l4 + 8] = m1;
        }
    }
    __syncthreads();
    float M0 = fmaxf(pm[ms + l4],     pm[64 + ms + l4]);
    float M1 = fmaxf(pm[ms + l4 + 8], pm[64 + ms + l4 + 8]);
    {
        float s0 = 0.f, s1 = 0.f;
        #pragma unroll
        for (int jc = 0; jc < 4; ++jc) {
            s[jc][0] = __expf(s[jc][0] - M0);
            s[jc][1] = __expf(s[jc][1] - M0);
            s[jc][2] = __expf(s[jc][2] - M1);
            s[jc][3] = __expf(s[jc][3] - M1);
            s0 += s[jc][0] + s[jc][1];
            s1 += s[jc][2] + s[jc][3];
        }
        s0 += __shfl_xor_sync(0xffffffffu, s0, 1);
        s0 += __shfl_xor_sync(0xffffffffu, s0, 2);
        s1 += __shfl_xor_sync(0xffffffffu, s1, 1);
        s1 += __shfl_xor_sync(0xffffffffu, s1, 2);
        if (l2 == 0) {
            ps[(w >> 2) * 64 + ms + l4]     = s0;
            ps[(w >> 2) * 64 + ms + l4 + 8] = s1;
        }
    }
    __syncthreads();
    {
        float inv0 = 1.0f / (ps[ms + l4]     + ps[64 + ms + l4]);
        float inv1 = 1.0f / (ps[ms + l4 + 8] + ps[64 + ms + l4 + 8]);
        #pragma unroll
        for (int jc = 0; jc < 4; ++jc)
            #pragma unroll
            for (int q = 0; q < 2; ++q) {
                int row = ms + l4 + q * 8;
                int j0  = ns + jc * 8 + l2 * 2;
                float inv = q ? inv1 : inv0;
                float p0 = s[jc][q * 2] * inv, p1 = s[jc][q * 2 + 1] * inv;
                __half h0 = __float2half(p0), h1 = __float2half(p1);
                __half lo0 = __float2half(p0 - __half2float(h0));
                __half lo1 = __float2half(p1 - __half2float(h1));
                uint32_t off = l128(row, j0 >> 3) + (j0 & 7) * 2;
                *(__half2*)(am_raw + AT_P  + off) = __halves2half2(h0, h1);
                *(__half2*)(am_raw + AT_PL + off) = __halves2half2(lo0, lo1);
            }
    }
    __syncthreads();

    // ---- Wh/Ww masked row sums -> WW tile ----
    {
        int r = tid & 15, it0 = tid >> 4;
        for (int i = it0; i < 64; i += 16) {
            float wh = 0.f, ww = 0.f;
            if (r < 15) {
                int rowj = (i >> 3) - (r - 7);
                if (rowj >= 0 && rowj < 8) {
                    const __half* hp = (const __half*)(am_raw + AT_P  + l128(i, rowj));
                    const __half* lp = (const __half*)(am_raw + AT_PL + l128(i, rowj));
                    #pragma unroll
                    for (int t = 0; t < 8; ++t)
                        wh += __half2float(hp[t]) + __half2float(lp[t]);
                }
                int colj = (i & 7) - (r - 7);
                if (colj >= 0 && colj < 8) {
                    #pragma unroll
                    for (int rj = 0; rj < 8; ++rj) {
                        ww += __half2float(*(const __half*)(am_raw + AT_P  + l128(i, rj) + colj * 2))
                            + __half2float(*(const __half*)(am_raw + AT_PL + l128(i, rj) + colj * 2));
                    }
                }
            }
            __half hwh = __float2half(wh), hww = __float2half(ww);
            int cw = r + 16;
            *(unsigned short*)(am_raw + AT_WW + l64(i, r >> 3)  + (r  & 7) * 2) = *(unsigned short*)&hwh;
            *(unsigned short*)(am_raw + AT_WW + l64(i, cw >> 3) + (cw & 7) * 2) = *(unsigned short*)&hww;
        }
    }
    __syncthreads();

    // ---- ctx: P·V (trans-B) + WW·EC (trans-B) ----
    {
        float o[4][4];
        #pragma unroll
        for (int j = 0; j < 4; ++j) { o[j][0]=o[j][1]=o[j][2]=o[j][3]=0.f; }
        int trow = (lane & 7) + ((lane >> 3) & 1) * 8;
        int tsel = lane >> 4;

        #pragma unroll
        for (int kk = 0; kk < 4; ++kk) {
            int c = 2 * kk + lc;
            uint32_t ph[4], pl[4];
            uint32_t offp = l128(ms + lrow, c);
            ldsm4(ph, sb + AT_P  + offp);
            ldsm4(pl, sb + AT_PL + offp);
            #pragma unroll
            for (int jp = 0; jp < 2; ++jp) {
                uint32_t bv[4];
                ldsm4t(bv, sb + AT_V + l128(kk * 16 + trow, (ns >> 3) + jp * 2 + tsel));
                mma16816(o[jp * 2],     ph, bv[0], bv[1]);
                mma16816(o[jp * 2],     pl, bv[0], bv[1]);
                mma16816(o[jp * 2 + 1], ph, bv[2], bv[3]);
                mma16816(o[jp * 2 + 1], pl, bv[2], bv[3]);
            }
        }
        #pragma unroll
        for (int kk2 = 0; kk2 < 2; ++kk2) {
            uint32_t aw_[4];
            ldsm4(aw_, sb + AT_WW + l64(ms + lrow, 2 * kk2 + lc));
            #pragma unroll
            for (int jp = 0; jp < 2; ++jp) {
                uint32_t ev[4];
                ldsm4t(ev, sb + AT_EC + l128(kk2 * 16 + trow, (ns >> 3) + jp * 2 + tsel));
                mma16816(o[jp * 2],     aw_, ev[0], ev[1]);
                mma16816(o[jp * 2 + 1], aw_, ev[2], ev[3]);
            }
        }
        #pragma unroll
        for (int jc = 0; jc < 4; ++jc) {
            int d = ns + jc * 8 + l2 * 2;
            int i = ms + l4;
            *(__half2*)(g_a + (size_t)(b * 64 + i) * DD + h * 64 + d) =
                __halves2half2(__float2half(o[jc][0]), __float2half(o[jc][1]));
            *(__half2*)(g_a + (size_t)(b * 64 + i + 8) * DD + h * 64 + d) =
                __halves2half2(__float2half(o[jc][2]), __float2half(o[jc][3]));
        }
    }
}

// ---------------------------------------------------------------------------
extern "C" void kernel_launch(void* const* d_in, const int* in_sizes, int n_in,
                              void* d_out, int out_size) {
    const float* x    = (const float*)d_in[0];
    const float* wq   = (const float*)d_in[1];
    const float* wk   = (const float*)d_in[2];
    const float* wv   = (const float*)d_in[3];
    const float* wo   = (const float*)d_in[4];
    const float* bo   = (const float*)d_in[5];
    const float* eq_h = (const float*)d_in[6];
    const float* eq_w = (const float*)d_in[7];
    const float* ek_h = (const float*)d_in[8];
    const float* ek_w = (const float*)d_in[9];
    const float* ev_h = (const float*)d_in[10];
    const float* ev_w = (const float*)d_in[11];
    float* out = (float*)d_out;

    cudaFuncSetAttribute(qkv_hmma, cudaFuncAttributeMaxDynamicSharedMemorySize, GEMM_SMEM);
    cudaFuncSetAttribute(out_hmma, cudaFuncAttributeMaxDynamicSharedMemorySize, GEMM_SMEM);
    cudaFuncSetAttribute(attn_mma, cudaFuncAttributeMaxDynamicSharedMemorySize, AT_BYTES);

    mega_prep<<<6184, 256>>>(x, wq, wk, wv, wo, eq_h, eq_w, ek_h, ek_w, ev_h, ev_w);
    qkv_hmma<<<dim3(24, 128), 512, GEMM_SMEM>>>();
    attn_mma<<<BB * HH, 256, AT_BYTES>>>();
    out_hmma<<<dim3(8, 128), 512, GEMM_SMEM>>>(bo, out);
}

// round 14
// speedup vs baseline: 1.2108x; 1.0484x over previous
#include <cuda_runtime.h>
#include <cuda_fp16.h>
#include <cstdint>

// Problem constants
#define BB 256
#define SS 64
#define DD 1024
#define HH 16
#define DH 64
#define NREL 15
#define MTOT (BB*SS)   // 16384
#define XELEMS ((size_t)MTOT*DD)

// ---------------------------------------------------------------------------
// Device scratch
// ---------------------------------------------------------------------------
__device__ float g_c[SS*SS];

__device__ __align__(1024) __half g_a [(size_t)MTOT*DD];      // x, then ctx (fp16)
__device__ __align__(1024) __half g_wh[(size_t)4*DD*DD];      // weights fp16

__device__ __align__(1024) __half g_qh[(size_t)MTOT*DD];
__device__ __align__(1024) __half g_kh[(size_t)MTOT*DD];
__device__ __align__(1024) __half g_vh[(size_t)MTOT*DD];

// pre-swizzled fp16 table tiles
__device__ __align__(16) __half g_ektiles[4096];   // 4 x 16rows x 64 (L128)
__device__ __align__(16) __half g_ectile[2048];    // [evh|pad|evw|pad] 32 x 64 (L128)

// ---------------------------------------------------------------------------
// PTX helpers
// ---------------------------------------------------------------------------
__device__ __forceinline__ uint32_t smem_u32(const void* p) {
    uint32_t a;
    asm("{ .reg .u64 t; cvta.to.shared.u64 t, %1; cvt.u32.u64 %0, t; }" : "=r"(a) : "l"(p));
    return a;
}
__device__ __forceinline__ void cp16(uint32_t dst, const void* src) {
    asm volatile("cp.async.cg.shared.global [%0], [%1], 16;" :: "r"(dst), "l"(src));
}
__device__ __forceinline__ void cp_commit() {
    asm volatile("cp.async.commit_group;" ::: "memory");
}
template<int N> __device__ __forceinline__ void cp_wait() {
    asm volatile("cp.async.wait_group %0;" :: "n"(N) : "memory");
}
__device__ __forceinline__ void ldsm4(uint32_t (&r)[4], uint32_t a) {
    asm volatile("ldmatrix.sync.aligned.m8n8.x4.shared.b16 {%0,%1,%2,%3}, [%4];"
                 : "=r"(r[0]), "=r"(r[1]), "=r"(r[2]), "=r"(r[3]) : "r"(a));
}
__device__ __forceinline__ void ldsm4t(uint32_t (&r)[4], uint32_t a) {
    asm volatile("ldmatrix.sync.aligned.m8n8.x4.trans.shared.b16 {%0,%1,%2,%3}, [%4];"
                 : "=r"(r[0]), "=r"(r[1]), "=r"(r[2]), "=r"(r[3]) : "r"(a));
}
__device__ __forceinline__ void mma16816(float (&c)[4], const uint32_t (&a)[4],
                                         uint32_t b0, uint32_t b1) {
    asm volatile("mma.sync.aligned.m16n8k16.row.col.f32.f16.f16.f32 "
                 "{%0,%1,%2,%3}, {%4,%5,%6,%7}, {%8,%9}, {%0,%1,%2,%3};"
                 : "+f"(c[0]), "+f"(c[1]), "+f"(c[2]), "+f"(c[3])
                 : "r"(a[0]), "r"(a[1]), "r"(a[2]), "r"(a[3]), "r"(b0), "r"(b1));
}

__device__ __forceinline__ uint32_t l128(int r, int c) {
    return (uint32_t)(r * 128 + (((c ^ (r & 7)) & 7) << 4));
}
__device__ __forceinline__ uint32_t l64(int r, int c) {
    return (uint32_t)(r * 64 + (((c ^ (r >> 1)) & 3) << 4));
}

// ---------------------------------------------------------------------------
// mega_prep: one launch does everything upstream of qkv_hmma.
// ---------------------------------------------------------------------------
__global__ __launch_bounds__(256) void mega_prep(
    const float* __restrict__ x,
    const float* __restrict__ w0, const float* __restrict__ w1,
    const float* __restrict__ w2, const float* __restrict__ w3,
    const float* __restrict__ eq_h, const float* __restrict__ eq_w,
    const float* __restrict__ ek_h, const float* __restrict__ ek_w,
    const float* __restrict__ ev_h, const float* __restrict__ ev_w)
{
    int bid = blockIdx.x;
    int tid = threadIdx.x;

    if (bid < 4096) {
        size_t base = ((size_t)bid * 256 + tid) * 16;
        #pragma unroll
        for (int half8 = 0; half8 < 2; ++half8) {
            size_t bb = base + half8 * 8;
            float4 a = *(const float4*)(x + bb);
            float4 c = *(const float4*)(x + bb + 4);
            float v[8] = {a.x, a.y, a.z, a.w, c.x, c.y, c.z, c.w};
            __half h[8];
            #pragma unroll
            for (int i = 0; i < 8; ++i) h[i] = __float2half(v[i]);
            *(uint4*)(g_a + bb) = *(uint4*)h;
        }
    } else if (bid < 6144) {
        int blk = bid - 4096;
        int which = blk >> 9;
        const float* src = (which == 0) ? w0 : (which == 1) ? w1 : (which == 2) ? w2 : w3;
        size_t lbase = ((size_t)(blk & 511) * 256 + tid) * 8;
        float4 a = *(const float4*)(src + lbase);
        float4 c = *(const float4*)(src + lbase + 4);
        float v[8] = {a.x, a.y, a.z, a.w, c.x, c.y, c.z, c.w};
        __half h[8];
        #pragma unroll
        for (int i = 0; i < 8; ++i) h[i] = __float2half(v[i]);
        *(uint4*)(g_wh + (size_t)which * DD * DD + lbase) = *(uint4*)h;
    } else if (bid < 6160) {
        int idx = (bid - 6144) * 256 + tid;
        int i = idx >> 6, j = idx & 63;
        int rr = (i >> 3) - (j >> 3) + 7;
        int rc = (i & 7) - (j & 7) + 7;
        float acc = 0.f;
        #pragma unroll 8
        for (int d = 0; d < 64; ++d) {
            float a = eq_h[rr * 64 + d] + eq_w[rc * 64 + d];
            float b = ek_h[rr * 64 + d] + ek_w[rc * 64 + d];
            acc += a * b;
        }
        g_c[idx] = acc;
    } else {
        int idx = (bid - 6160) * 256 + tid;
        if (idx < 4096) {
            int t = idx >> 10, r = (idx >> 6) & 15, d = idx & 63;
            const float* src = (t == 0) ? ek_h : (t == 1) ? ek_w : (t == 2) ? eq_h : eq_w;
            __half v = __float2half((r < 15) ? src[r * 64 + d] : 0.f);
            *(unsigned short*)((char*)g_ektiles + t * 2048 + l128(r, d >> 3) + (d & 7) * 2) =
                *(unsigned short*)&v;
        } else {
            int e = idx - 4096;
            int r = e >> 6, d = e & 63;
            float f = 0.f;
            if (r < 15) f = ev_h[r * 64 + d];
            else if (r >= 16 && r < 31) f = ev_w[(r - 16) * 64 + d];
            __half v = __float2half(f);
            *(unsigned short*)((char*)g_ectile + l128(r, d >> 3) + (d & 7) * 2) =
                *(unsigned short*)&v;
        }
    }
}

// ---------------------------------------------------------------------------
// HMMA fp16 GEMM core (exact R8): acc(128x128) = A * W^T, K=1024.
// ---------------------------------------------------------------------------
#define STAGES 4
#define STAGE_BYTES 16384
#define GEMM_SMEM (STAGES * STAGE_BYTES)

__device__ __forceinline__ void gemm_acc(
    const __half* __restrict__ Ap, const __half* __restrict__ Bp,
    int mbase, int nbase, float acc[2][4][4])
{
    extern __shared__ unsigned char sm_raw[];
    uint32_t smbase = smem_u32(sm_raw);
    int tid = threadIdx.x, lane = tid & 31, wid = tid >> 5;
    int wm = (wid >> 2) * 32, wn = (wid & 3) * 32;

    #pragma unroll
    for (int i = 0; i < 2; ++i)
        #pragma unroll
        for (int j = 0; j < 4; ++j)
            #pragma unroll
            for (int e = 0; e < 4; ++e) acc[i][j][e] = 0.f;

    const __half* srcA = Ap + (size_t)mbase * DD;
    const __half* srcB = Bp + (size_t)nbase * DD;

    int lm  = tid >> 2;
    int lk8 = tid & 3;
    uint32_t loff = (uint32_t)(lm * 64 + ((lk8 ^ (lm >> 1)) & 3) * 16);

    #define LOAD_CHUNK(kc, st) do {                                            \
        uint32_t sb_ = smbase + (st) * STAGE_BYTES;                            \
        size_t g_ = (size_t)lm * DD + (kc) * 32 + lk8 * 8;                     \
        cp16(sb_ + loff,        srcA + g_);                                    \
        cp16(sb_ + 8192 + loff, srcB + g_);                                    \
        cp_commit();                                                           \
    } while (0)

    LOAD_CHUNK(0, 0);
    LOAD_CHUNK(1, 1);
    LOAD_CHUNK(2, 2);

    int arow = wm + (lane & 7) + ((lane >> 3) & 1) * 8;
    int brow = wn + (lane & 7) + ((lane >> 3) & 1) * 8;
    int k8l  = (lane >> 4);

    for (int kc = 0; kc < 32; ++kc) {
        cp_wait<2>();
        __syncthreads();
        if (kc + 3 < 32) LOAD_CHUNK(kc + 3, (kc + 3) & 3);
        else             cp_commit();
        uint32_t sb = smbase + (kc & 3) * STAGE_BYTES;

        #pragma unroll
        for (int s16 = 0; s16 < 2; ++s16) {
            int k8 = 2 * s16 + k8l;
            uint32_t av[2][4];
            #pragma unroll
            for (int i = 0; i < 2; ++i) {
                int r = arow + i * 16;
                uint32_t ad = sb + (uint32_t)(r * 64 + ((k8 ^ (r >> 1)) & 3) * 16);
                ldsm4(av[i], ad);
            }
            uint32_t bv[2][4];
            #pragma unroll
            for (int jp = 0; jp < 2; ++jp) {
                int r = brow + jp * 16;
                uint32_t ad = sb + 8192 + (uint32_t)(r * 64 + ((k8 ^ (r >> 1)) & 3) * 16);
                ldsm4(bv[jp], ad);
            }
            #pragma unroll
            for (int i = 0; i < 2; ++i)
                #pragma unroll
                for (int j = 0; j < 4; ++j)
                    mma16816(acc[i][j], av[i],
                             bv[j >> 1][j & 1], bv[j >> 1][(j & 1) + 2]);
        }
    }
    #undef LOAD_CHUNK
}

// ---------------------------------------------------------------------------
// QKV GEMM: epilogue writes single fp16 q/k/v into (B,H,S,DH)
// ---------------------------------------------------------------------------
__global__ __launch_bounds__(512, 1) void qkv_hmma() {
    int nt = blockIdx.x, mt = blockIdx.y;
    int which = nt >> 3, nq = nt & 7;
    float acc[2][4][4];
    gemm_acc(g_a, g_wh + (size_t)which * DD * DD, mt * 128, nq * 128, acc);

    __half* dh = (which == 0) ? g_qh : (which == 1) ? g_kh : g_vh;
    int lane = threadIdx.x & 31, wid = threadIdx.x >> 5;
    int wm = (wid >> 2) * 32, wn = (wid & 3) * 32;
    int l4 = lane >> 2, l2 = (lane & 3) * 2;

    #pragma unroll
    for (int i = 0; i < 2; ++i)
        #pragma unroll
        for (int j = 0; j < 4; ++j) {
            int m = mt * 128 + wm + i * 16 + l4;
            int n = nq * 128 + wn + j * 8 + l2;
            int h = n >> 6, d = n & 63;
            int b = m >> 6, s = m & 63;
            size_t i0 = ((size_t)((b * HH + h) * SS + s)) * 64 + d;
            size_t i1 = ((size_t)((b * HH + h) * SS + s + 8)) * 64 + d;
            *(__half2*)(dh + i0) = __halves2half2(__float2half(acc[i][j][0]),
                                                  __float2half(acc[i][j][1]));
            *(__half2*)(dh + i1) = __halves2half2(__float2half(acc[i][j][2]),
                                                  __float2half(acc[i][j][3]));
        }
}

// ---------------------------------------------------------------------------
// Output GEMM: out = ctx @ wo^T + bo
// ---------------------------------------------------------------------------
__global__ __launch_bounds__(512, 1) void out_hmma(const float* __restrict__ bo,
                                                   float* __restrict__ out) {
    int nt = blockIdx.x, mt = blockIdx.y;
    float acc[2][4][4];
    gemm_acc(g_a, g_wh + (size_t)3 * DD * DD, mt * 128, nt * 128, acc);

    int lane = threadIdx.x & 31, wid = threadIdx.x >> 5;
    int wm = (wid >> 2) * 32, wn = (wid & 3) * 32;
    int l4 = lane >> 2, l2 = (lane & 3) * 2;

    #pragma unroll
    for (int i = 0; i < 2; ++i)
        #pragma unroll
        for (int j = 0; j < 4; ++j) {
            int m = mt * 128 + wm + i * 16 + l4;
            int n = nt * 128 + wn + j * 8 + l2;
            float b0 = __ldg(bo + n), b1 = __ldg(bo + n + 1);
            *(float2*)&out[(size_t)m * DD + n] =
                make_float2(acc[i][j][0] + b0, acc[i][j][1] + b1);
            *(float2*)&out[(size_t)(m + 8) * DD + n] =
                make_float2(acc[i][j][2] + b0, acc[i][j][3] + b1);
        }
}

// ---------------------------------------------------------------------------
// MMA attention v4: 1-term S (plain fp16 q/k), P hi/lo kept. 76.8KB smem.
// ---------------------------------------------------------------------------
#define AT_Q   0
#define AT_K   8192
#define AT_V   16384
#define AT_EK  24576
#define AT_EC  32768
#define AT_WW  36864
#define AT_T   40960
#define AT_P   59392
#define AT_PL  67584
#define AT_PM  75776
#define AT_PS  76288
#define AT_BYTES 76800

__global__ __launch_bounds__(256, 2) void attn_mma() {
    extern __shared__ unsigned char am_raw[];
    uint32_t sb = smem_u32(am_raw);
    int tid = threadIdx.x, lane = tid & 31, w = tid >> 5;
    int bx = blockIdx.x;
    int b = bx >> 4, h = bx & 15;
    size_t gbase = (size_t)bx * 4096;

    #pragma unroll
    for (int it = 0; it < 2; ++it) {
        int e = it * 256 + tid;
        int r = e >> 3, c = e & 7;
        uint32_t off = l128(r, c);
        size_t g = gbase + r * 64 + c * 8;
        cp16(sb + AT_Q + off, g_qh + g);
        cp16(sb + AT_K + off, g_kh + g);
        cp16(sb + AT_V + off, g_vh + g);
        cp16(sb + AT_EK + e * 16, (const char*)g_ektiles + e * 16);
        if (it == 0)
            cp16(sb + AT_EC + tid * 16, (const char*)g_ectile + tid * 16);
    }
    cp_commit();
    cp_wait<0>();
    __syncthreads();

    int ms = (w & 3) * 16, ns = (w >> 2) * 32;
    int lrow = (lane & 7) + ((lane >> 3) & 1) * 8;
    int lc   = lane >> 4;
    int l4 = lane >> 2, l2 = lane & 3;

    // ---- Phase 1: S (1-term) + table mmas ----
    float s[4][4];
    float t0[2][4], t1[2][4];
    #pragma unroll
    for (int j = 0; j < 4; ++j) {
        s[j][0]=s[j][1]=s[j][2]=s[j][3]=0.f;
        if (j < 2) { t0[j][0]=t0[j][1]=t0[j][2]=t0[j][3]=0.f;
                     t1[j][0]=t1[j][1]=t1[j][2]=t1[j][3]=0.f; }
    }
    #pragma unroll
    for (int kk = 0; kk < 4; ++kk) {
        int c = 2 * kk + lc;
        uint32_t ah[4];
        uint32_t offq = l128(ms + lrow, c);
        ldsm4(ah, sb + AT_Q + offq);
        uint32_t bh[2][4];
        #pragma unroll
        for (int jp = 0; jp < 2; ++jp)
            ldsm4(bh[jp], sb + AT_K + l128(ns + jp * 16 + lrow, c));
        #pragma unroll
        for (int j = 0; j < 4; ++j)
            mma16816(s[j], ah, bh[j >> 1][j & 1], bh[j >> 1][(j & 1) + 2]);
        uint32_t ta[4];
        if (w < 4) { ta[0]=ah[0]; ta[1]=ah[1]; ta[2]=ah[2]; ta[3]=ah[3]; }
        else       ldsm4(ta, sb + AT_K + offq);
        uint32_t e0[4], e1[4];
        int tb = (w < 4) ? 0 : 2;
        uint32_t offe = l128(lrow, c);
        ldsm4(e0, sb + AT_EK + tb * 2048 + offe);
        ldsm4(e1, sb + AT_EK + (tb + 1) * 2048 + offe);
        #pragma unroll
        for (int jc = 0; jc < 2; ++jc) {
            mma16816(t0[jc], ta, e0[jc], e0[jc + 2]);
            mma16816(t1[jc], ta, e1[jc], e1[jc + 2]);
        }
    }
    // store table frags (fp32 stride 18)
    {
        unsigned char* tb0 = am_raw + AT_T + ((w < 4) ? 0 : 2 * 4608);
        #pragma unroll
        for (int jc = 0; jc < 2; ++jc) {
            int r0 = jc * 8 + l2 * 2;
            int i0 = ms + l4;
            *(float2*)(tb0 + (size_t)(i0 * 18 + r0) * 4)        = make_float2(t0[jc][0], t0[jc][1]);
            *(float2*)(tb0 + (size_t)((i0 + 8) * 18 + r0) * 4)  = make_float2(t0[jc][2], t0[jc][3]);
            *(float2*)(tb0 + 4608 + (size_t)(i0 * 18 + r0) * 4)       = make_float2(t1[jc][0], t1[jc][1]);
            *(float2*)(tb0 + 4608 + (size_t)((i0 + 8) * 18 + r0) * 4) = make_float2(t1[jc][2], t1[jc][3]);
        }
    }
    __syncthreads();

    // ---- bias in registers ----
    {
        const float* Ah = (const float*)(am_raw + AT_T);
        const float* Aw = Ah + 1152;
        const float* Ch = Aw + 1152;
        const float* Cw = Ch + 1152;
        #pragma unroll
        for (int jc = 0; jc < 4; ++jc)
            #pragma unroll
            for (int q = 0; q < 2; ++q)
                #pragma unroll
                for (int p = 0; p < 2; ++p) {
                    int i = ms + l4 + q * 8;
                    int j = ns + jc * 8 + l2 * 2 + p;
                    int rr = (i >> 3) - (j >> 3) + 7;
                    int rc = (i & 7) - (j & 7) + 7;
                    s[jc][q * 2 + p] = (s[jc][q * 2 + p]
                        + Ah[i * 18 + rr] + Aw[i * 18 + rc]
                        + Ch[j * 18 + rr] + Cw[j * 18 + rc]
                        + __ldg(&g_c[i * 64 + j])) * 0.125f;
                }
    }

    // ---- register softmax ----
    float* pm = (float*)(am_raw + AT_PM);
    float* ps = (float*)(am_raw + AT_PS);
    {
        float m0 = -1e30f, m1 = -1e30f;
        #pragma unroll
        for (int jc = 0; jc < 4; ++jc) {
            m0 = fmaxf(m0, fmaxf(s[jc][0], s[jc][1]));
            m1 = fmaxf(m1, fmaxf(s[jc][2], s[jc][3]));
        }
        m0 = fmaxf(m0, __shfl_xor_sync(0xffffffffu, m0, 1));
        m0 = fmaxf(m0, __shfl_xor_sync(0xffffffffu, m0, 2));
        m1 = fmaxf(m1, __shfl_xor_sync(0xffffffffu, m1, 1));
        m1 = fmaxf(m1, __shfl_xor_sync(0xffffffffu, m1, 2));
        if (l2 == 0) {
            pm[(w >> 2) * 64 + ms + l4]     = m0;
            pm[(w >> 2) * 64 + ms + l4 + 8] = m1;
        }
    }
    __syncthreads();
    float M0 = fmaxf(pm[ms + l4],     pm[64 + ms + l4]);
    float M1 = fmaxf(pm[ms + l4 + 8], pm[64 + ms + l4 + 8]);
    {
        float s0 = 0.f, s1 = 0.f;
        #pragma unroll
        for (int jc = 0; jc < 4; ++jc) {
            s[jc][0] = __expf(s[jc][0] - M0);
            s[jc][1] = __expf(s[jc][1] - M0);
            s[jc][2] = __expf(s[jc][2] - M1);
            s[jc][3] = __expf(s[jc][3] - M1);
            s0 += s[jc][0] + s[jc][1];
            s1 += s[jc][2] + s[jc][3];
        }
        s0 += __shfl_xor_sync(0xffffffffu, s0, 1);
        s0 += __shfl_xor_sync(0xffffffffu, s0, 2);
        s1 += __shfl_xor_sync(0xffffffffu, s1, 1);
        s1 += __shfl_xor_sync(0xffffffffu, s1, 2);
        if (l2 == 0) {
            ps[(w >> 2) * 64 + ms + l4]     = s0;
            ps[(w >> 2) * 64 + ms + l4 + 8] = s1;
        }
    }
    __syncthreads();
    {
        float inv0 = 1.0f / (ps[ms + l4]     + ps[64 + ms + l4]);
        float inv1 = 1.0f / (ps[ms + l4 + 8] + ps[64 + ms + l4 + 8]);
        #pragma unroll
        for (int jc = 0; jc < 4; ++jc)
            #pragma unroll
            for (int q = 0; q < 2; ++q) {
                int row = ms + l4 + q * 8;
                int j0  = ns + jc * 8 + l2 * 2;
                float inv = q ? inv1 : inv0;
                float p0 = s[jc][q * 2] * inv, p1 = s[jc][q * 2 + 1] * inv;
                __half h0 = __float2half(p0), h1 = __float2half(p1);
                __half lo0 = __float2half(p0 - __half2float(h0));
                __half lo1 = __float2half(p1 - __half2float(h1));
                uint32_t off = l128(row, j0 >> 3) + (j0 & 7) * 2;
                *(__half2*)(am_raw + AT_P  + off) = __halves2half2(h0, h1);
                *(__half2*)(am_raw + AT_PL + off) = __halves2half2(lo0, lo1);
            }
    }
    __syncthreads();

    // ---- Wh/Ww masked row sums -> WW tile ----
    {
        int r = tid & 15, it0 = tid >> 4;
        for (int i = it0; i < 64; i += 16) {
            float wh = 0.f, ww = 0.f;
            if (r < 15) {
                int rowj = (i >> 3) - (r - 7);
                if (rowj >= 0 && rowj < 8) {
                    const __half* hp = (const __half*)(am_raw + AT_P  + l128(i, rowj));
                    const __half* lp = (const __half*)(am_raw + AT_PL + l128(i, rowj));
                    #pragma unroll
                    for (int t = 0; t < 8; ++t)
                        wh += __half2float(hp[t]) + __half2float(lp[t]);
                }
                int colj = (i & 7) - (r - 7);
                if (colj >= 0 && colj < 8) {
                    #pragma unroll
                    for (int rj = 0; rj < 8; ++rj) {
                        ww += __half2float(*(const __half*)(am_raw + AT_P  + l128(i, rj) + colj * 2))
                            + __half2float(*(const __half*)(am_raw + AT_PL + l128(i, rj) + colj * 2));
                    }
                }
            }
            __half hwh = __float2half(wh), hww = __float2half(ww);
            int cw = r + 16;
            *(unsigned short*)(am_raw + AT_WW + l64(i, r >> 3)  + (r  & 7) * 2) = *(unsigned short*)&hwh;
            *(unsigned short*)(am_raw + AT_WW + l64(i, cw >> 3) + (cw & 7) * 2) = *(unsigned short*)&hww;
        }
    }
    __syncthreads();

    // ---- ctx: P·V (trans-B, 2-term) + WW·EC (trans-B) ----
    {
        float o[4][4];
        #pragma unroll
        for (int j = 0; j < 4; ++j) { o[j][0]=o[j][1]=o[j][2]=o[j][3]=0.f; }
        int trow = (lane & 7) + ((lane >> 3) & 1) * 8;
        int tsel = lane >> 4;

        #pragma unroll
        for (int kk = 0; kk < 4; ++kk) {
            int c = 2 * kk + lc;
            uint32_t ph[4], pl[4];
            uint32_t offp = l128(ms + lrow, c);
            ldsm4(ph, sb + AT_P  + offp);
            ldsm4(pl, sb + AT_PL + offp);
            #pragma unroll
            for (int jp = 0; jp < 2; ++jp) {
                uint32_t bv[4];
                ldsm4t(bv, sb + AT_V + l128(kk * 16 + trow, (ns >> 3) + jp * 2 + tsel));
                mma16816(o[jp * 2],     ph, bv[0], bv[1]);
                mma16816(o[jp * 2],     pl, bv[0], bv[1]);
                mma16816(o[jp * 2 + 1], ph, bv[2], bv[3]);
                mma16816(o[jp * 2 + 1], pl, bv[2], bv[3]);
            }
        }
        #pragma unroll
        for (int kk2 = 0; kk2 < 2; ++kk2) {
            uint32_t aw_[4];
            ldsm4(aw_, sb + AT_WW + l64(ms + lrow, 2 * kk2 + lc));
            #pragma unroll
            for (int jp = 0; jp < 2; ++jp) {
                uint32_t ev[4];
                ldsm4t(ev, sb + AT_EC + l128(kk2 * 16 + trow, (ns >> 3) + jp * 2 + tsel));
                mma16816(o[jp * 2],     aw_, ev[0], ev[1]);
                mma16816(o[jp * 2 + 1], aw_, ev[2], ev[3]);
            }
        }
        #pragma unroll
        for (int jc = 0; jc < 4; ++jc) {
            int d = ns + jc * 8 + l2 * 2;
            int i = ms + l4;
            *(__half2*)(g_a + (size_t)(b * 64 + i) * DD + h * 64 + d) =
                __halves2half2(__float2half(o[jc][0]), __float2half(o[jc][1]));
            *(__half2*)(g_a + (size_t)(b * 64 + i + 8) * DD + h * 64 + d) =
                __halves2half2(__float2half(o[jc][2]), __float2half(o[jc][3]));
        }
    }
}

// ---------------------------------------------------------------------------
extern "C" void kernel_launch(void* const* d_in, const int* in_sizes, int n_in,
                              void* d_out, int out_size) {
    const float* x    = (const float*)d_in[0];
    const float* wq   = (const float*)d_in[1];
    const float* wk   = (const float*)d_in[2];
    const float* wv   = (const float*)d_in[3];
    const float* wo   = (const float*)d_in[4];
    const float* bo   = (const float*)d_in[5];
    const float* eq_h = (const float*)d_in[6];
    const float* eq_w = (const float*)d_in[7];
    const float* ek_h = (const float*)d_in[8];
    const float* ek_w = (const float*)d_in[9];
    const float* ev_h = (const float*)d_in[10];
    const float* ev_w = (const float*)d_in[11];
    float* out = (float*)d_out;

    cudaFuncSetAttribute(qkv_hmma, cudaFuncAttributeMaxDynamicSharedMemorySize, GEMM_SMEM);
    cudaFuncSetAttribute(out_hmma, cudaFuncAttributeMaxDynamicSharedMemorySize, GEMM_SMEM);
    cudaFuncSetAttribute(attn_mma, cudaFuncAttributeMaxDynamicSharedMemorySize, AT_BYTES);

    mega_prep<<<6184, 256>>>(x, wq, wk, wv, wo, eq_h, eq_w, ek_h, ek_w, ev_h, ev_w);
    qkv_hmma<<<dim3(24, 128), 512, GEMM_SMEM>>>();
    attn_mma<<<BB * HH, 256, AT_BYTES>>>();
    out_hmma<<<dim3(8, 128), 512, GEMM_SMEM>>>(bo, out);
}

// round 16
// speedup vs baseline: 1.3252x; 1.0945x over previous
#include <cuda_runtime.h>
#include <cuda_fp16.h>
#include <cstdint>

// Problem constants
#define BB 256
#define SS 64
#define DD 1024
#define HH 16
#define DH 64
#define NREL 15
#define MTOT (BB*SS)   // 16384
#define XELEMS ((size_t)MTOT*DD)

// ---------------------------------------------------------------------------
// Device scratch
// ---------------------------------------------------------------------------
__device__ float g_c[SS*SS];

__device__ __align__(1024) __half g_a [(size_t)MTOT*DD];      // x, then ctx (fp16)
__device__ __align__(1024) __half g_wh[(size_t)4*DD*DD];      // weights fp16

__device__ __align__(1024) __half g_qh[(size_t)MTOT*DD];
__device__ __align__(1024) __half g_kh[(size_t)MTOT*DD];
__device__ __align__(1024) __half g_vh[(size_t)MTOT*DD];

// pre-swizzled fp16 table tiles
__device__ __align__(16) __half g_ektiles[4096];   // 4 x 16rows x 64 (L128)
__device__ __align__(16) __half g_ectile[2048];    // [evh|pad|evw|pad] 32 x 64 (L128)

// ---------------------------------------------------------------------------
// PTX helpers
// ---------------------------------------------------------------------------
__device__ __forceinline__ uint32_t smem_u32(const void* p) {
    uint32_t a;
    asm("{ .reg .u64 t; cvta.to.shared.u64 t, %1; cvt.u32.u64 %0, t; }" : "=r"(a) : "l"(p));
    return a;
}
__device__ __forceinline__ void cp16(uint32_t dst, const void* src) {
    asm volatile("cp.async.cg.shared.global [%0], [%1], 16;" :: "r"(dst), "l"(src));
}
__device__ __forceinline__ void cp_commit() {
    asm volatile("cp.async.commit_group;" ::: "memory");
}
template<int N> __device__ __forceinline__ void cp_wait() {
    asm volatile("cp.async.wait_group %0;" :: "n"(N) : "memory");
}
__device__ __forceinline__ void ldsm4(uint32_t (&r)[4], uint32_t a) {
    asm volatile("ldmatrix.sync.aligned.m8n8.x4.shared.b16 {%0,%1,%2,%3}, [%4];"
                 : "=r"(r[0]), "=r"(r[1]), "=r"(r[2]), "=r"(r[3]) : "r"(a));
}
__device__ __forceinline__ void ldsm4t(uint32_t (&r)[4], uint32_t a) {
    asm volatile("ldmatrix.sync.aligned.m8n8.x4.trans.shared.b16 {%0,%1,%2,%3}, [%4];"
                 : "=r"(r[0]), "=r"(r[1]), "=r"(r[2]), "=r"(r[3]) : "r"(a));
}
__device__ __forceinline__ void mma16816(float (&c)[4], const uint32_t (&a)[4],
                                         uint32_t b0, uint32_t b1) {
    asm volatile("mma.sync.aligned.m16n8k16.row.col.f32.f16.f16.f32 "
                 "{%0,%1,%2,%3}, {%4,%5,%6,%7}, {%8,%9}, {%0,%1,%2,%3};"
                 : "+f"(c[0]), "+f"(c[1]), "+f"(c[2]), "+f"(c[3])
                 : "r"(a[0]), "r"(a[1]), "r"(a[2]), "r"(a[3]), "r"(b0), "r"(b1));
}

__device__ __forceinline__ uint32_t l128(int r, int c) {
    return (uint32_t)(r * 128 + (((c ^ (r & 7)) & 7) << 4));
}
__device__ __forceinline__ uint32_t l64(int r, int c) {
    return (uint32_t)(r * 64 + (((c ^ (r >> 1)) & 3) << 4));
}

// ---------------------------------------------------------------------------
// mega_prep: one launch does everything upstream of qkv_hmma.
// ---------------------------------------------------------------------------
__global__ __launch_bounds__(256) void mega_prep(
    const float* __restrict__ x,
    const float* __restrict__ w0, const float* __restrict__ w1,
    const float* __restrict__ w2, const float* __restrict__ w3,
    const float* __restrict__ eq_h, const float* __restrict__ eq_w,
    const float* __restrict__ ek_h, const float* __restrict__ ek_w,
    const float* __restrict__ ev_h, const float* __restrict__ ev_w)
{
    int bid = blockIdx.x;
    int tid = threadIdx.x;

    if (bid < 4096) {
        size_t base = ((size_t)bid * 256 + tid) * 16;
        #pragma unroll
        for (int half8 = 0; half8 < 2; ++half8) {
            size_t bb = base + half8 * 8;
            float4 a = *(const float4*)(x + bb);
            float4 c = *(const float4*)(x + bb + 4);
            float v[8] = {a.x, a.y, a.z, a.w, c.x, c.y, c.z, c.w};
            __half h[8];
            #pragma unroll
            for (int i = 0; i < 8; ++i) h[i] = __float2half(v[i]);
            *(uint4*)(g_a + bb) = *(uint4*)h;
        }
    } else if (bid < 6144) {
        int blk = bid - 4096;
        int which = blk >> 9;
        const float* src = (which == 0) ? w0 : (which == 1) ? w1 : (which == 2) ? w2 : w3;
        size_t lbase = ((size_t)(blk & 511) * 256 + tid) * 8;
        float4 a = *(const float4*)(src + lbase);
        float4 c = *(const float4*)(src + lbase + 4);
        float v[8] = {a.x, a.y, a.z, a.w, c.x, c.y, c.z, c.w};
        __half h[8];
        #pragma unroll
        for (int i = 0; i < 8; ++i) h[i] = __float2half(v[i]);
        *(uint4*)(g_wh + (size_t)which * DD * DD + lbase) = *(uint4*)h;
    } else if (bid < 6160) {
        int idx = (bid - 6144) * 256 + tid;
        int i = idx >> 6, j = idx & 63;
        int rr = (i >> 3) - (j >> 3) + 7;
        int rc = (i & 7) - (j & 7) + 7;
        float acc = 0.f;
        #pragma unroll 8
        for (int d = 0; d < 64; ++d) {
            float a = eq_h[rr * 64 + d] + eq_w[rc * 64 + d];
            float b = ek_h[rr * 64 + d] + ek_w[rc * 64 + d];
            acc += a * b;
        }
        g_c[idx] = acc;
    } else {
        int idx = (bid - 6160) * 256 + tid;
        if (idx < 4096) {
            int t = idx >> 10, r = (idx >> 6) & 15, d = idx & 63;
            const float* src = (t == 0) ? ek_h : (t == 1) ? ek_w : (t == 2) ? eq_h : eq_w;
            __half v = __float2half((r < 15) ? src[r * 64 + d] : 0.f);
            *(unsigned short*)((char*)g_ektiles + t * 2048 + l128(r, d >> 3) + (d & 7) * 2) =
                *(unsigned short*)&v;
        } else {
            int e = idx - 4096;
            int r = e >> 6, d = e & 63;
            float f = 0.f;
            if (r < 15) f = ev_h[r * 64 + d];
            else if (r >= 16 && r < 31) f = ev_w[(r - 16) * 64 + d];
            __half v = __float2half(f);
            *(unsigned short*)((char*)g_ectile + l128(r, d >> 3) + (d & 7) * 2) =
                *(unsigned short*)&v;
        }
    }
}

// ---------------------------------------------------------------------------
// HMMA fp16 GEMM core: acc(128x128) = A * W^T, K=1024.
// 512 threads, 16 warps (4x4), warp tile 32x32, 4-stage 16KB ring.
// Targeted at 2 CTAs/SM (64-reg cap via launch bounds on callers).
// ---------------------------------------------------------------------------
#define STAGES 4
#define STAGE_BYTES 16384
#define GEMM_SMEM (STAGES * STAGE_BYTES)

__device__ __forceinline__ void gemm_acc(
    const __half* __restrict__ Ap, const __half* __restrict__ Bp,
    int mbase, int nbase, float acc[2][4][4])
{
    extern __shared__ unsigned char sm_raw[];
    uint32_t smbase = smem_u32(sm_raw);
    int tid = threadIdx.x, lane = tid & 31, wid = tid >> 5;
    int wm = (wid >> 2) * 32, wn = (wid & 3) * 32;

    #pragma unroll
    for (int i = 0; i < 2; ++i)
        #pragma unroll
        for (int j = 0; j < 4; ++j)
            #pragma unroll
            for (int e = 0; e < 4; ++e) acc[i][j][e] = 0.f;

    const __half* srcA = Ap + (size_t)mbase * DD;
    const __half* srcB = Bp + (size_t)nbase * DD;

    int lm  = tid >> 2;
    int lk8 = tid & 3;
    uint32_t loff = (uint32_t)(lm * 64 + ((lk8 ^ (lm >> 1)) & 3) * 16);

    #define LOAD_CHUNK(kc, st) do {                                            \
        uint32_t sb_ = smbase + (st) * STAGE_BYTES;                            \
        size_t g_ = (size_t)lm * DD + (kc) * 32 + lk8 * 8;                     \
        cp16(sb_ + loff,        srcA + g_);                                    \
        cp16(sb_ + 8192 + loff, srcB + g_);                                    \
        cp_commit();                                                           \
    } while (0)

    LOAD_CHUNK(0, 0);
    LOAD_CHUNK(1, 1);
    LOAD_CHUNK(2, 2);

    int arow = wm + (lane & 7) + ((lane >> 3) & 1) * 8;
    int brow = wn + (lane & 7) + ((lane >> 3) & 1) * 8;
    int k8l  = (lane >> 4);

    for (int kc = 0; kc < 32; ++kc) {
        cp_wait<2>();
        __syncthreads();
        if (kc + 3 < 32) LOAD_CHUNK(kc + 3, (kc + 3) & 3);
        else             cp_commit();
        uint32_t sb = smbase + (kc & 3) * STAGE_BYTES;

        #pragma unroll
        for (int s16 = 0; s16 < 2; ++s16) {
            int k8 = 2 * s16 + k8l;
            uint32_t av[2][4];
            #pragma unroll
            for (int i = 0; i < 2; ++i) {
                int r = arow + i * 16;
                uint32_t ad = sb + (uint32_t)(r * 64 + ((k8 ^ (r >> 1)) & 3) * 16);
                ldsm4(av[i], ad);
            }
            uint32_t bv[2][4];
            #pragma unroll
            for (int jp = 0; jp < 2; ++jp) {
                int r = brow + jp * 16;
                uint32_t ad = sb + 8192 + (uint32_t)(r * 64 + ((k8 ^ (r >> 1)) & 3) * 16);
                ldsm4(bv[jp], ad);
            }
            #pragma unroll
            for (int i = 0; i < 2; ++i)
                #pragma unroll
                for (int j = 0; j < 4; ++j)
                    mma16816(acc[i][j], av[i],
                             bv[j >> 1][j & 1], bv[j >> 1][(j & 1) + 2]);
        }
    }
    #undef LOAD_CHUNK
}

// ---------------------------------------------------------------------------
// QKV GEMM: epilogue writes single fp16 q/k/v into (B,H,S,DH)
// ---------------------------------------------------------------------------
__global__ __launch_bounds__(512, 2) void qkv_hmma() {
    int nt = blockIdx.x, mt = blockIdx.y;
    int which = nt >> 3, nq = nt & 7;
    float acc[2][4][4];
    gemm_acc(g_a, g_wh + (size_t)which * DD * DD, mt * 128, nq * 128, acc);

    __half* dh = (which == 0) ? g_qh : (which == 1) ? g_kh : g_vh;
    int lane = threadIdx.x & 31, wid = threadIdx.x >> 5;
    int wm = (wid >> 2) * 32, wn = (wid & 3) * 32;
    int l4 = lane >> 2, l2 = (lane & 3) * 2;

    #pragma unroll
    for (int i = 0; i < 2; ++i)
        #pragma unroll
        for (int j = 0; j < 4; ++j) {
            int m = mt * 128 + wm + i * 16 + l4;
            int n = nq * 128 + wn + j * 8 + l2;
            int h = n >> 6, d = n & 63;
            int b = m >> 6, s = m & 63;
            size_t i0 = ((size_t)((b * HH + h) * SS + s)) * 64 + d;
            size_t i1 = ((size_t)((b * HH + h) * SS + s + 8)) * 64 + d;
            *(__half2*)(dh + i0) = __halves2half2(__float2half(acc[i][j][0]),
                                                  __float2half(acc[i][j][1]));
            *(__half2*)(dh + i1) = __halves2half2(__float2half(acc[i][j][2]),
                                                  __float2half(acc[i][j][3]));
        }
}

// ---------------------------------------------------------------------------
// Output GEMM: out = ctx @ wo^T + bo
// ---------------------------------------------------------------------------
__global__ __launch_bounds__(512, 2) void out_hmma(const float* __restrict__ bo,
                                                   float* __restrict__ out) {
    int nt = blockIdx.x, mt = blockIdx.y;
    float acc[2][4][4];
    gemm_acc(g_a, g_wh + (size_t)3 * DD * DD, mt * 128, nt * 128, acc);

    int lane = threadIdx.x & 31, wid = threadIdx.x >> 5;
    int wm = (wid >> 2) * 32, wn = (wid & 3) * 32;
    int l4 = lane >> 2, l2 = (lane & 3) * 2;

    #pragma unroll
    for (int i = 0; i < 2; ++i)
        #pragma unroll
        for (int j = 0; j < 4; ++j) {
            int m = mt * 128 + wm + i * 16 + l4;
            int n = nt * 128 + wn + j * 8 + l2;
            float b0 = __ldg(bo + n), b1 = __ldg(bo + n + 1);
            *(float2*)&out[(size_t)m * DD + n] =
                make_float2(acc[i][j][0] + b0, acc[i][j][1] + b1);
            *(float2*)&out[(size_t)(m + 8) * DD + n] =
                make_float2(acc[i][j][2] + b0, acc[i][j][3] + b1);
        }
}

// ---------------------------------------------------------------------------
// MMA attention v4 (R14 best, unchanged): 1-term S, P hi/lo. 76.8KB.
// ---------------------------------------------------------------------------
#define AT_Q   0
#define AT_K   8192
#define AT_V   16384
#define AT_EK  24576
#define AT_EC  32768
#define AT_WW  36864
#define AT_T   40960
#define AT_P   59392
#define AT_PL  67584
#define AT_PM  75776
#define AT_PS  76288
#define AT_BYTES 76800

__global__ __launch_bounds__(256, 2) void attn_mma() {
    extern __shared__ unsigned char am_raw[];
    uint32_t sb = smem_u32(am_raw);
    int tid = threadIdx.x, lane = tid & 31, w = tid >> 5;
    int bx = blockIdx.x;
    int b = bx >> 4, h = bx & 15;
    size_t gbase = (size_t)bx * 4096;

    #pragma unroll
    for (int it = 0; it < 2; ++it) {
        int e = it * 256 + tid;
        int r = e >> 3, c = e & 7;
        uint32_t off = l128(r, c);
        size_t g = gbase + r * 64 + c * 8;
        cp16(sb + AT_Q + off, g_qh + g);
        cp16(sb + AT_K + off, g_kh + g);
        cp16(sb + AT_V + off, g_vh + g);
        cp16(sb + AT_EK + e * 16, (const char*)g_ektiles + e * 16);
        if (it == 0)
            cp16(sb + AT_EC + tid * 16, (const char*)g_ectile + tid * 16);
    }
    cp_commit();
    cp_wait<0>();
    __syncthreads();

    int ms = (w & 3) * 16, ns = (w >> 2) * 32;
    int lrow = (lane & 7) + ((lane >> 3) & 1) * 8;
    int lc   = lane >> 4;
    int l4 = lane >> 2, l2 = lane & 3;

    // ---- Phase 1: S (1-term) + table mmas ----
    float s[4][4];
    float t0[2][4], t1[2][4];
    #pragma unroll
    for (int j = 0; j < 4; ++j) {
        s[j][0]=s[j][1]=s[j][2]=s[j][3]=0.f;
        if (j < 2) { t0[j][0]=t0[j][1]=t0[j][2]=t0[j][3]=0.f;
                     t1[j][0]=t1[j][1]=t1[j][2]=t1[j][3]=0.f; }
    }
    #pragma unroll
    for (int kk = 0; kk < 4; ++kk) {
        int c = 2 * kk + lc;
        uint32_t ah[4];
        uint32_t offq = l128(ms + lrow, c);
        ldsm4(ah, sb + AT_Q + offq);
        uint32_t bh[2][4];
        #pragma unroll
        for (int jp = 0; jp < 2; ++jp)
            ldsm4(bh[jp], sb + AT_K + l128(ns + jp * 16 + lrow, c));
        #pragma unroll
        for (int j = 0; j < 4; ++j)
            mma16816(s[j], ah, bh[j >> 1][j & 1], bh[j >> 1][(j & 1) + 2]);
        uint32_t ta[4];
        if (w < 4) { ta[0]=ah[0]; ta[1]=ah[1]; ta[2]=ah[2]; ta[3]=ah[3]; }
        else       ldsm4(ta, sb + AT_K + offq);
        uint32_t e0[4], e1[4];
        int tb = (w < 4) ? 0 : 2;
        uint32_t offe = l128(lrow, c);
        ldsm4(e0, sb + AT_EK + tb * 2048 + offe);
        ldsm4(e1, sb + AT_EK + (tb + 1) * 2048 + offe);
        #pragma unroll
        for (int jc = 0; jc < 2; ++jc) {
            mma16816(t0[jc], ta, e0[jc], e0[jc + 2]);
            mma16816(t1[jc], ta, e1[jc], e1[jc + 2]);
        }
    }
    // store table frags (fp32 stride 18)
    {
        unsigned char* tb0 = am_raw + AT_T + ((w < 4) ? 0 : 2 * 4608);
        #pragma unroll
        for (int jc = 0; jc < 2; ++jc) {
            int r0 = jc * 8 + l2 * 2;
            int i0 = ms + l4;
            *(float2*)(tb0 + (size_t)(i0 * 18 + r0) * 4)        = make_float2(t0[jc][0], t0[jc][1]);
            *(float2*)(tb0 + (size_t)((i0 + 8) * 18 + r0) * 4)  = make_float2(t0[jc][2], t0[jc][3]);
            *(float2*)(tb0 + 4608 + (size_t)(i0 * 18 + r0) * 4)       = make_float2(t1[jc][0], t1[jc][1]);
            *(float2*)(tb0 + 4608 + (size_t)((i0 + 8) * 18 + r0) * 4) = make_float2(t1[jc][2], t1[jc][3]);
        }
    }
    __syncthreads();

    // ---- bias in registers ----
    {
        const float* Ah = (const float*)(am_raw + AT_T);
        const float* Aw = Ah + 1152;
        const float* Ch = Aw + 1152;
        const float* Cw = Ch + 1152;
        #pragma unroll
        for (int jc = 0; jc < 4; ++jc)
            #pragma unroll
            for (int q = 0; q < 2; ++q)
                #pragma unroll
                for (int p = 0; p < 2; ++p) {
                    int i = ms + l4 + q * 8;
                    int j = ns + jc * 8 + l2 * 2 + p;
                    int rr = (i >> 3) - (j >> 3) + 7;
                    int rc = (i & 7) - (j & 7) + 7;
                    s[jc][q * 2 + p] = (s[jc][q * 2 + p]
                        + Ah[i * 18 + rr] + Aw[i * 18 + rc]
                        + Ch[j * 18 + rr] + Cw[j * 18 + rc]
                        + __ldg(&g_c[i * 64 + j])) * 0.125f;
                }
    }

    // ---- register softmax ----
    float* pm = (float*)(am_raw + AT_PM);
    float* ps = (float*)(am_raw + AT_PS);
    {
        float m0 = -1e30f, m1 = -1e30f;
        #pragma unroll
        for (int jc = 0; jc < 4; ++jc) {
            m0 = fmaxf(m0, fmaxf(s[jc][0], s[jc][1]));
            m1 = fmaxf(m1, fmaxf(s[jc][2], s[jc][3]));
        }
        m0 = fmaxf(m0, __shfl_xor_sync(0xffffffffu, m0, 1));
        m0 = fmaxf(m0, __shfl_xor_sync(0xffffffffu, m0, 2));
        m1 = fmaxf(m1, __shfl_xor_sync(0xffffffffu, m1, 1));
        m1 = fmaxf(m1, __shfl_xor_sync(0xffffffffu, m1, 2));
        if (l2 == 0) {
            pm[(w >> 2) * 64 + ms + l4]     = m0;
            pm[(w >> 2) * 64 + ms + l4 + 8] = m1;
        }
    }
    __syncthreads();
    float M0 = fmaxf(pm[ms + l4],     pm[64 + ms + l4]);
    float M1 = fmaxf(pm[ms + l4 + 8], pm[64 + ms + l4 + 8]);
    {
        float s0 = 0.f, s1 = 0.f;
        #pragma unroll
        for (int jc = 0; jc < 4; ++jc) {
            s[jc][0] = __expf(s[jc][0] - M0);
            s[jc][1] = __expf(s[jc][1] - M0);
            s[jc][2] = __expf(s[jc][2] - M1);
            s[jc][3] = __expf(s[jc][3] - M1);
            s0 += s[jc][0] + s[jc][1];
            s1 += s[jc][2] + s[jc][3];
        }
        s0 += __shfl_xor_sync(0xffffffffu, s0, 1);
        s0 += __shfl_xor_sync(0xffffffffu, s0, 2);
        s1 += __shfl_xor_sync(0xffffffffu, s1, 1);
        s1 += __shfl_xor_sync(0xffffffffu, s1, 2);
        if (l2 == 0) {
            ps[(w >> 2) * 64 + ms + l4]     = s0;
            ps[(w >> 2) * 64 + ms + l4 + 8] = s1;
        }
    }
    __syncthreads();
    {
        float inv0 = 1.0f / (ps[ms + l4]     + ps[64 + ms + l4]);
        float inv1 = 1.0f / (ps[ms + l4 + 8] + ps[64 + ms + l4 + 8]);
        #pragma unroll
        for (int jc = 0; jc < 4; ++jc)
            #pragma unroll
            for (int q = 0; q < 2; ++q) {
                int row = ms + l4 + q * 8;
                int j0  = ns + jc * 8 + l2 * 2;
                float inv = q ? inv1 : inv0;
                float p0 = s[jc][q * 2] * inv, p1 = s[jc][q * 2 + 1] * inv;
                __half h0 = __float2half(p0), h1 = __float2half(p1);
                __half lo0 = __float2half(p0 - __half2float(h0));
                __half lo1 = __float2half(p1 - __half2float(h1));
                uint32_t off = l128(row, j0 >> 3) + (j0 & 7) * 2;
                *(__half2*)(am_raw + AT_P  + off) = __halves2half2(h0, h1);
                *(__half2*)(am_raw + AT_PL + off) = __halves2half2(lo0, lo1);
            }
    }
    __syncthreads();

    // ---- Wh/Ww masked row sums -> WW tile ----
    {
        int r = tid & 15, it0 = tid >> 4;
        for (int i = it0; i < 64; i += 16) {
            float wh = 0.f, ww = 0.f;
            if (r < 15) {
                int rowj = (i >> 3) - (r - 7);
                if (rowj >= 0 && rowj < 8) {
                    const __half* hp = (const __half*)(am_raw + AT_P  + l128(i, rowj));
                    const __half* lp = (const __half*)(am_raw + AT_PL + l128(i, rowj));
                    #pragma unroll
                    for (int t = 0; t < 8; ++t)
                        wh += __half2float(hp[t]) + __half2float(lp[t]);
                }
                int colj = (i & 7) - (r - 7);
                if (colj >= 0 && colj < 8) {
                    #pragma unroll
                    for (int rj = 0; rj < 8; ++rj) {
                        ww += __half2float(*(const __half*)(am_raw + AT_P  + l128(i, rj) + colj * 2))
                            + __half2float(*(const __half*)(am_raw + AT_PL + l128(i, rj) + colj * 2));
                    }
                }
            }
            __half hwh = __float2half(wh), hww = __float2half(ww);
            int cw = r + 16;
            *(unsigned short*)(am_raw + AT_WW + l64(i, r >> 3)  + (r  & 7) * 2) = *(unsigned short*)&hwh;
            *(unsigned short*)(am_raw + AT_WW + l64(i, cw >> 3) + (cw & 7) * 2) = *(unsigned short*)&hww;
        }
    }
    __syncthreads();

    // ---- ctx: P·V (trans-B, 2-term) + WW·EC (trans-B) ----
    {
        float o[4][4];
        #pragma unroll
        for (int j = 0; j < 4; ++j) { o[j][0]=o[j][1]=o[j][2]=o[j][3]=0.f; }
        int trow = (lane & 7) + ((lane >> 3) & 1) * 8;
        int tsel = lane >> 4;

        #pragma unroll
        for (int kk = 0; kk < 4; ++kk) {
            int c = 2 * kk + lc;
            uint32_t ph[4], pl[4];
            uint32_t offp = l128(ms + lrow, c);
            ldsm4(ph, sb + AT_P  + offp);
            ldsm4(pl, sb + AT_PL + offp);
            #pragma unroll
            for (int jp = 0; jp < 2; ++jp) {
                uint32_t bv[4];
                ldsm4t(bv, sb + AT_V + l128(kk * 16 + trow, (ns >> 3) + jp * 2 + tsel));
                mma16816(o[jp * 2],     ph, bv[0], bv[1]);
                mma16816(o[jp * 2],     pl, bv[0], bv[1]);
                mma16816(o[jp * 2 + 1], ph, bv[2], bv[3]);
                mma16816(o[jp * 2 + 1], pl, bv[2], bv[3]);
            }
        }
        #pragma unroll
        for (int kk2 = 0; kk2 < 2; ++kk2) {
            uint32_t aw_[4];
            ldsm4(aw_, sb + AT_WW + l64(ms + lrow, 2 * kk2 + lc));
            #pragma unroll
            for (int jp = 0; jp < 2; ++jp) {
                uint32_t ev[4];
                ldsm4t(ev, sb + AT_EC + l128(kk2 * 16 + trow, (ns >> 3) + jp * 2 + tsel));
                mma16816(o[jp * 2],     aw_, ev[0], ev[1]);
                mma16816(o[jp * 2 + 1], aw_, ev[2], ev[3]);
            }
        }
        #pragma unroll
        for (int jc = 0; jc < 4; ++jc) {
            int d = ns + jc * 8 + l2 * 2;
            int i = ms + l4;
            *(__half2*)(g_a + (size_t)(b * 64 + i) * DD + h * 64 + d) =
                __halves2half2(__float2half(o[jc][0]), __float2half(o[jc][1]));
            *(__half2*)(g_a + (size_t)(b * 64 + i + 8) * DD + h * 64 + d) =
                __halves2half2(__float2half(o[jc][2]), __float2half(o[jc][3]));
        }
    }
}

// ---------------------------------------------------------------------------
extern "C" void kernel_launch(void* const* d_in, const int* in_sizes, int n_in,
                              void* d_out, int out_size) {
    const float* x    = (const float*)d_in[0];
    const float* wq   = (const float*)d_in[1];
    const float* wk   = (const float*)d_in[2];
    const float* wv   = (const float*)d_in[3];
    const float* wo   = (const float*)d_in[4];
    const float* bo   = (const float*)d_in[5];
    const float* eq_h = (const float*)d_in[6];
    const float* eq_w = (const float*)d_in[7];
    const float* ek_h = (const float*)d_in[8];
    const float* ek_w = (const float*)d_in[9];
    const float* ev_h = (const float*)d_in[10];
    const float* ev_w = (const float*)d_in[11];
    float* out = (float*)d_out;

    cudaFuncSetAttribute(qkv_hmma, cudaFuncAttributeMaxDynamicSharedMemorySize, GEMM_SMEM);
    cudaFuncSetAttribute(out_hmma, cudaFuncAttributeMaxDynamicSharedMemorySize, GEMM_SMEM);
    cudaFuncSetAttribute(attn_mma, cudaFuncAttributeMaxDynamicSharedMemorySize, AT_BYTES);

    mega_prep<<<6184, 256>>>(x, wq, wk, wv, wo, eq_h, eq_w, ek_h, ek_w, ev_h, ev_w);
    qkv_hmma<<<dim3(24, 128), 512, GEMM_SMEM>>>();
    attn_mma<<<BB * HH, 256, AT_BYTES>>>();
    out_hmma<<<dim3(8, 128), 512, GEMM_SMEM>>>(bo, out);
}

// round 17
// speedup vs baseline: 1.3479x; 1.0171x over previous
#include <cuda_runtime.h>
#include <cuda_fp16.h>
#include <cstdint>

// Problem constants
#define BB 256
#define SS 64
#define DD 1024
#define HH 16
#define DH 64
#define NREL 15
#define MTOT (BB*SS)   // 16384
#define XELEMS ((size_t)MTOT*DD)

// ---------------------------------------------------------------------------
// Device scratch
// ---------------------------------------------------------------------------
__device__ float g_c[SS*SS];

__device__ __align__(1024) __half g_a [(size_t)MTOT*DD];      // x, then ctx (fp16)
__device__ __align__(1024) __half g_wh[(size_t)4*DD*DD];      // weights fp16

__device__ __align__(1024) __half g_qh[(size_t)MTOT*DD];
__device__ __align__(1024) __half g_kh[(size_t)MTOT*DD];
__device__ __align__(1024) __half g_vh[(size_t)MTOT*DD];

// pre-swizzled fp16 table tiles
__device__ __align__(16) __half g_ektiles[4096];   // 4 x 16rows x 64 (L128)
__device__ __align__(16) __half g_ectile[2048];    // [evh|pad|evw|pad] 32 x 64 (L128)

// ---------------------------------------------------------------------------
// PTX helpers
// ---------------------------------------------------------------------------
__device__ __forceinline__ uint32_t smem_u32(const void* p) {
    uint32_t a;
    asm("{ .reg .u64 t; cvta.to.shared.u64 t, %1; cvt.u32.u64 %0, t; }" : "=r"(a) : "l"(p));
    return a;
}
__device__ __forceinline__ void cp16(uint32_t dst, const void* src) {
    asm volatile("cp.async.cg.shared.global [%0], [%1], 16;" :: "r"(dst), "l"(src));
}
__device__ __forceinline__ void cp_commit() {
    asm volatile("cp.async.commit_group;" ::: "memory");
}
template<int N> __device__ __forceinline__ void cp_wait() {
    asm volatile("cp.async.wait_group %0;" :: "n"(N) : "memory");
}
__device__ __forceinline__ void ldsm4(uint32_t (&r)[4], uint32_t a) {
    asm volatile("ldmatrix.sync.aligned.m8n8.x4.shared.b16 {%0,%1,%2,%3}, [%4];"
                 : "=r"(r[0]), "=r"(r[1]), "=r"(r[2]), "=r"(r[3]) : "r"(a));
}
__device__ __forceinline__ void ldsm4t(uint32_t (&r)[4], uint32_t a) {
    asm volatile("ldmatrix.sync.aligned.m8n8.x4.trans.shared.b16 {%0,%1,%2,%3}, [%4];"
                 : "=r"(r[0]), "=r"(r[1]), "=r"(r[2]), "=r"(r[3]) : "r"(a));
}
__device__ __forceinline__ void mma16816(float (&c)[4], const uint32_t (&a)[4],
                                         uint32_t b0, uint32_t b1) {
    asm volatile("mma.sync.aligned.m16n8k16.row.col.f32.f16.f16.f32 "
                 "{%0,%1,%2,%3}, {%4,%5,%6,%7}, {%8,%9}, {%0,%1,%2,%3};"
                 : "+f"(c[0]), "+f"(c[1]), "+f"(c[2]), "+f"(c[3])
                 : "r"(a[0]), "r"(a[1]), "r"(a[2]), "r"(a[3]), "r"(b0), "r"(b1));
}

__device__ __forceinline__ uint32_t l128(int r, int c) {
    return (uint32_t)(r * 128 + (((c ^ (r & 7)) & 7) << 4));
}
__device__ __forceinline__ uint32_t l64(int r, int c) {
    return (uint32_t)(r * 64 + (((c ^ (r >> 1)) & 3) << 4));
}

// ---------------------------------------------------------------------------
// mega_prep: one launch does everything upstream of qkv_hmma.
// ---------------------------------------------------------------------------
__global__ __launch_bounds__(256) void mega_prep(
    const float* __restrict__ x,
    const float* __restrict__ w0, const float* __restrict__ w1,
    const float* __restrict__ w2, const float* __restrict__ w3,
    const float* __restrict__ eq_h, const float* __restrict__ eq_w,
    const float* __restrict__ ek_h, const float* __restrict__ ek_w,
    const float* __restrict__ ev_h, const float* __restrict__ ev_w)
{
    int bid = blockIdx.x;
    int tid = threadIdx.x;

    if (bid < 4096) {
        size_t base = ((size_t)bid * 256 + tid) * 16;
        #pragma unroll
        for (int half8 = 0; half8 < 2; ++half8) {
            size_t bb = base + half8 * 8;
            float4 a = *(const float4*)(x + bb);
            float4 c = *(const float4*)(x + bb + 4);
            float v[8] = {a.x, a.y, a.z, a.w, c.x, c.y, c.z, c.w};
            __half h[8];
            #pragma unroll
            for (int i = 0; i < 8; ++i) h[i] = __float2half(v[i]);
            *(uint4*)(g_a + bb) = *(uint4*)h;
        }
    } else if (bid < 6144) {
        int blk = bid - 4096;
        int which = blk >> 9;
        const float* src = (which == 0) ? w0 : (which == 1) ? w1 : (which == 2) ? w2 : w3;
        size_t lbase = ((size_t)(blk & 511) * 256 + tid) * 8;
        float4 a = *(const float4*)(src + lbase);
        float4 c = *(const float4*)(src + lbase + 4);
        float v[8] = {a.x, a.y, a.z, a.w, c.x, c.y, c.z, c.w};
        __half h[8];
        #pragma unroll
        for (int i = 0; i < 8; ++i) h[i] = __float2half(v[i]);
        *(uint4*)(g_wh + (size_t)which * DD * DD + lbase) = *(uint4*)h;
    } else if (bid < 6160) {
        int idx = (bid - 6144) * 256 + tid;
        int i = idx >> 6, j = idx & 63;
        int rr = (i >> 3) - (j >> 3) + 7;
        int rc = (i & 7) - (j & 7) + 7;
        float acc = 0.f;
        #pragma unroll 8
        for (int d = 0; d < 64; ++d) {
            float a = eq_h[rr * 64 + d] + eq_w[rc * 64 + d];
            float b = ek_h[rr * 64 + d] + ek_w[rc * 64 + d];
            acc += a * b;
        }
        g_c[idx] = acc;
    } else {
        int idx = (bid - 6160) * 256 + tid;
        if (idx < 4096) {
            int t = idx >> 10, r = (idx >> 6) & 15, d = idx & 63;
            const float* src = (t == 0) ? ek_h : (t == 1) ? ek_w : (t == 2) ? eq_h : eq_w;
            __half v = __float2half((r < 15) ? src[r * 64 + d] : 0.f);
            *(unsigned short*)((char*)g_ektiles + t * 2048 + l128(r, d >> 3) + (d & 7) * 2) =
                *(unsigned short*)&v;
        } else {
            int e = idx - 4096;
            int r = e >> 6, d = e & 63;
            float f = 0.f;
            if (r < 15) f = ev_h[r * 64 + d];
            else if (r >= 16 && r < 31) f = ev_w[(r - 16) * 64 + d];
            __half v = __float2half(f);
            *(unsigned short*)((char*)g_ectile + l128(r, d >> 3) + (d & 7) * 2) =
                *(unsigned short*)&v;
        }
    }
}

// ---------------------------------------------------------------------------
// HMMA fp16 GEMM core: acc(128x128) = A * W^T, K=1024.
// 512 threads, 16 warps (4x4), warp tile 32x32, 4-stage 16KB ring.
// 2 CTAs/SM via 64-reg cap on callers.
// ---------------------------------------------------------------------------
#define STAGES 4
#define STAGE_BYTES 16384
#define GEMM_SMEM (STAGES * STAGE_BYTES)

__device__ __forceinline__ void gemm_acc(
    const __half* __restrict__ Ap, const __half* __restrict__ Bp,
    int mbase, int nbase, float acc[2][4][4])
{
    extern __shared__ unsigned char sm_raw[];
    uint32_t smbase = smem_u32(sm_raw);
    int tid = threadIdx.x, lane = tid & 31, wid = tid >> 5;
    int wm = (wid >> 2) * 32, wn = (wid & 3) * 32;

    #pragma unroll
    for (int i = 0; i < 2; ++i)
        #pragma unroll
        for (int j = 0; j < 4; ++j)
            #pragma unroll
            for (int e = 0; e < 4; ++e) acc[i][j][e] = 0.f;

    const __half* srcA = Ap + (size_t)mbase * DD;
    const __half* srcB = Bp + (size_t)nbase * DD;

    int lm  = tid >> 2;
    int lk8 = tid & 3;
    uint32_t loff = (uint32_t)(lm * 64 + ((lk8 ^ (lm >> 1)) & 3) * 16);

    #define LOAD_CHUNK(kc, st) do {                                            \
        uint32_t sb_ = smbase + (st) * STAGE_BYTES;                            \
        size_t g_ = (size_t)lm * DD + (kc) * 32 + lk8 * 8;                     \
        cp16(sb_ + loff,        srcA + g_);                                    \
        cp16(sb_ + 8192 + loff, srcB + g_);                                    \
        cp_commit();                                                           \
    } while (0)

    LOAD_CHUNK(0, 0);
    LOAD_CHUNK(1, 1);
    LOAD_CHUNK(2, 2);

    int arow = wm + (lane & 7) + ((lane >> 3) & 1) * 8;
    int brow = wn + (lane & 7) + ((lane >> 3) & 1) * 8;
    int k8l  = (lane >> 4);

    for (int kc = 0; kc < 32; ++kc) {
        cp_wait<2>();
        __syncthreads();
        if (kc + 3 < 32) LOAD_CHUNK(kc + 3, (kc + 3) & 3);
        else             cp_commit();
        uint32_t sb = smbase + (kc & 3) * STAGE_BYTES;

        #pragma unroll
        for (int s16 = 0; s16 < 2; ++s16) {
            int k8 = 2 * s16 + k8l;
            uint32_t av[2][4];
            #pragma unroll
            for (int i = 0; i < 2; ++i) {
                int r = arow + i * 16;
                uint32_t ad = sb + (uint32_t)(r * 64 + ((k8 ^ (r >> 1)) & 3) * 16);
                ldsm4(av[i], ad);
            }
            uint32_t bv[2][4];
            #pragma unroll
            for (int jp = 0; jp < 2; ++jp) {
                int r = brow + jp * 16;
                uint32_t ad = sb + 8192 + (uint32_t)(r * 64 + ((k8 ^ (r >> 1)) & 3) * 16);
                ldsm4(bv[jp], ad);
            }
            #pragma unroll
            for (int i = 0; i < 2; ++i)
                #pragma unroll
                for (int j = 0; j < 4; ++j)
                    mma16816(acc[i][j], av[i],
                             bv[j >> 1][j & 1], bv[j >> 1][(j & 1) + 2]);
        }
    }
    #undef LOAD_CHUNK
}

// ---------------------------------------------------------------------------
// QKV GEMM: epilogue writes single fp16 q/k/v into (B,H,S,DH)
// ---------------------------------------------------------------------------
__global__ __launch_bounds__(512, 2) void qkv_hmma() {
    int nt = blockIdx.x, mt = blockIdx.y;
    int which = nt >> 3, nq = nt & 7;
    float acc[2][4][4];
    gemm_acc(g_a, g_wh + (size_t)which * DD * DD, mt * 128, nq * 128, acc);

    __half* dh = (which == 0) ? g_qh : (which == 1) ? g_kh : g_vh;
    int lane = threadIdx.x & 31, wid = threadIdx.x >> 5;
    int wm = (wid >> 2) * 32, wn = (wid & 3) * 32;
    int l4 = lane >> 2, l2 = (lane & 3) * 2;

    #pragma unroll
    for (int i = 0; i < 2; ++i)
        #pragma unroll
        for (int j = 0; j < 4; ++j) {
            int m = mt * 128 + wm + i * 16 + l4;
            int n = nq * 128 + wn + j * 8 + l2;
            int h = n >> 6, d = n & 63;
            int b = m >> 6, s = m & 63;
            size_t i0 = ((size_t)((b * HH + h) * SS + s)) * 64 + d;
            size_t i1 = ((size_t)((b * HH + h) * SS + s + 8)) * 64 + d;
            *(__half2*)(dh + i0) = __halves2half2(__float2half(acc[i][j][0]),
                                                  __float2half(acc[i][j][1]));
            *(__half2*)(dh + i1) = __halves2half2(__float2half(acc[i][j][2]),
                                                  __float2half(acc[i][j][3]));
        }
}

// ---------------------------------------------------------------------------
// Output GEMM: out = ctx @ wo^T + bo
// ---------------------------------------------------------------------------
__global__ __launch_bounds__(512, 2) void out_hmma(const float* __restrict__ bo,
                                                   float* __restrict__ out) {
    int nt = blockIdx.x, mt = blockIdx.y;
    float acc[2][4][4];
    gemm_acc(g_a, g_wh + (size_t)3 * DD * DD, mt * 128, nt * 128, acc);

    int lane = threadIdx.x & 31, wid = threadIdx.x >> 5;
    int wm = (wid >> 2) * 32, wn = (wid & 3) * 32;
    int l4 = lane >> 2, l2 = (lane & 3) * 2;

    #pragma unroll
    for (int i = 0; i < 2; ++i)
        #pragma unroll
        for (int j = 0; j < 4; ++j) {
            int m = mt * 128 + wm + i * 16 + l4;
            int n = nt * 128 + wn + j * 8 + l2;
            float b0 = __ldg(bo + n), b1 = __ldg(bo + n + 1);
            *(float2*)&out[(size_t)m * DD + n] =
                make_float2(acc[i][j][0] + b0, acc[i][j][1] + b1);
            *(float2*)&out[(size_t)(m + 8) * DD + n] =
                make_float2(acc[i][j][2] + b0, acc[i][j][3] + b1);
        }
}

// ---------------------------------------------------------------------------
// MMA attention v4: 1-term S, P hi/lo. 76.8KB smem; now 3 CTAs/SM
// (3 x 76800 = 230400 <= 233472; phase live set ~75 regs < 85 cap).
// ---------------------------------------------------------------------------
#define AT_Q   0
#define AT_K   8192
#define AT_V   16384
#define AT_EK  24576
#define AT_EC  32768
#define AT_WW  36864
#define AT_T   40960
#define AT_P   59392
#define AT_PL  67584
#define AT_PM  75776
#define AT_PS  76288
#define AT_BYTES 76800

__global__ __launch_bounds__(256, 3) void attn_mma() {
    extern __shared__ unsigned char am_raw[];
    uint32_t sb = smem_u32(am_raw);
    int tid = threadIdx.x, lane = tid & 31, w = tid >> 5;
    int bx = blockIdx.x;
    int b = bx >> 4, h = bx & 15;
    size_t gbase = (size_t)bx * 4096;

    #pragma unroll
    for (int it = 0; it < 2; ++it) {
        int e = it * 256 + tid;
        int r = e >> 3, c = e & 7;
        uint32_t off = l128(r, c);
        size_t g = gbase + r * 64 + c * 8;
        cp16(sb + AT_Q + off, g_qh + g);
        cp16(sb + AT_K + off, g_kh + g);
        cp16(sb + AT_V + off, g_vh + g);
        cp16(sb + AT_EK + e * 16, (const char*)g_ektiles + e * 16);
        if (it == 0)
            cp16(sb + AT_EC + tid * 16, (const char*)g_ectile + tid * 16);
    }
    cp_commit();
    cp_wait<0>();
    __syncthreads();

    int ms = (w & 3) * 16, ns = (w >> 2) * 32;
    int lrow = (lane & 7) + ((lane >> 3) & 1) * 8;
    int lc   = lane >> 4;
    int l4 = lane >> 2, l2 = lane & 3;

    // ---- Phase 1: S (1-term) + table mmas ----
    float s[4][4];
    float t0[2][4], t1[2][4];
    #pragma unroll
    for (int j = 0; j < 4; ++j) {
        s[j][0]=s[j][1]=s[j][2]=s[j][3]=0.f;
        if (j < 2) { t0[j][0]=t0[j][1]=t0[j][2]=t0[j][3]=0.f;
                     t1[j][0]=t1[j][1]=t1[j][2]=t1[j][3]=0.f; }
    }
    #pragma unroll
    for (int kk = 0; kk < 4; ++kk) {
        int c = 2 * kk + lc;
        uint32_t ah[4];
        uint32_t offq = l128(ms + lrow, c);
        ldsm4(ah, sb + AT_Q + offq);
        uint32_t bh[2][4];
        #pragma unroll
        for (int jp = 0; jp < 2; ++jp)
            ldsm4(bh[jp], sb + AT_K + l128(ns + jp * 16 + lrow, c));
        #pragma unroll
        for (int j = 0; j < 4; ++j)
            mma16816(s[j], ah, bh[j >> 1][j & 1], bh[j >> 1][(j & 1) + 2]);
        uint32_t ta[4];
        if (w < 4) { ta[0]=ah[0]; ta[1]=ah[1]; ta[2]=ah[2]; ta[3]=ah[3]; }
        else       ldsm4(ta, sb + AT_K + offq);
        uint32_t e0[4], e1[4];
        int tb = (w < 4) ? 0 : 2;
        uint32_t offe = l128(lrow, c);
        ldsm4(e0, sb + AT_EK + tb * 2048 + offe);
        ldsm4(e1, sb + AT_EK + (tb + 1) * 2048 + offe);
        #pragma unroll
        for (int jc = 0; jc < 2; ++jc) {
            mma16816(t0[jc], ta, e0[jc], e0[jc + 2]);
            mma16816(t1[jc], ta, e1[jc], e1[jc + 2]);
        }
    }
    // store table frags (fp32 stride 18)
    {
        unsigned char* tb0 = am_raw + AT_T + ((w < 4) ? 0 : 2 * 4608);
        #pragma unroll
        for (int jc = 0; jc < 2; ++jc) {
            int r0 = jc * 8 + l2 * 2;
            int i0 = ms + l4;
            *(float2*)(tb0 + (size_t)(i0 * 18 + r0) * 4)        = make_float2(t0[jc][0], t0[jc][1]);
            *(float2*)(tb0 + (size_t)((i0 + 8) * 18 + r0) * 4)  = make_float2(t0[jc][2], t0[jc][3]);
            *(float2*)(tb0 + 4608 + (size_t)(i0 * 18 + r0) * 4)       = make_float2(t1[jc][0], t1[jc][1]);
            *(float2*)(tb0 + 4608 + (size_t)((i0 + 8) * 18 + r0) * 4) = make_float2(t1[jc][2], t1[jc][3]);
        }
    }
    __syncthreads();

    // ---- bias in registers ----
    {
        const float* Ah = (const float*)(am_raw + AT_T);
        const float* Aw = Ah + 1152;
        const float* Ch = Aw + 1152;
        const float* Cw = Ch + 1152;
        #pragma unroll
        for (int jc = 0; jc < 4; ++jc)
            #pragma unroll
            for (int q = 0; q < 2; ++q)
                #pragma unroll
                for (int p = 0; p < 2; ++p) {
                    int i = ms + l4 + q * 8;
                    int j = ns + jc * 8 + l2 * 2 + p;
                    int rr = (i >> 3) - (j >> 3) + 7;
                    int rc = (i & 7) - (j & 7) + 7;
                    s[jc][q * 2 + p] = (s[jc][q * 2 + p]
                        + Ah[i * 18 + rr] + Aw[i * 18 + rc]
                        + Ch[j * 18 + rr] + Cw[j * 18 + rc]
                        + __ldg(&g_c[i * 64 + j])) * 0.125f;
                }
    }

    // ---- register softmax ----
    float* pm = (float*)(am_raw + AT_PM);
    float* ps = (float*)(am_raw + AT_PS);
    {
        float m0 = -1e30f, m1 = -1e30f;
        #pragma unroll
        for (int jc = 0; jc < 4; ++jc) {
            m0 = fmaxf(m0, fmaxf(s[jc][0], s[jc][1]));
            m1 = fmaxf(m1, fmaxf(s[jc][2], s[jc][3]));
        }
        m0 = fmaxf(m0, __shfl_xor_sync(0xffffffffu, m0, 1));
        m0 = fmaxf(m0, __shfl_xor_sync(0xffffffffu, m0, 2));
        m1 = fmaxf(m1, __shfl_xor_sync(0xffffffffu, m1, 1));
        m1 = fmaxf(m1, __shfl_xor_sync(0xffffffffu, m1, 2));
        if (l2 == 0) {
            pm[(w >> 2) * 64 + ms + l4]     = m0;
            pm[(w >> 2) * 64 + ms + l4 + 8] = m1;
        }
    }
    __syncthreads();
    float M0 = fmaxf(pm[ms + l4],     pm[64 + ms + l4]);
    float M1 = fmaxf(pm[ms + l4 + 8], pm[64 + ms + l4 + 8]);
    {
        float s0 = 0.f, s1 = 0.f;
        #pragma unroll
        for (int jc = 0; jc < 4; ++jc) {
            s[jc][0] = __expf(s[jc][0] - M0);
            s[jc][1] = __expf(s[jc][1] - M0);
            s[jc][2] = __expf(s[jc][2] - M1);
            s[jc][3] = __expf(s[jc][3] - M1);
            s0 += s[jc][0] + s[jc][1];
            s1 += s[jc][2] + s[jc][3];
        }
        s0 += __shfl_xor_sync(0xffffffffu, s0, 1);
        s0 += __shfl_xor_sync(0xffffffffu, s0, 2);
        s1 += __shfl_xor_sync(0xffffffffu, s1, 1);
        s1 += __shfl_xor_sync(0xffffffffu, s1, 2);
        if (l2 == 0) {
            ps[(w >> 2) * 64 + ms + l4]     = s0;
            ps[(w >> 2) * 64 + ms + l4 + 8] = s1;
        }
    }
    __syncthreads();
    {
        float inv0 = 1.0f / (ps[ms + l4]     + ps[64 + ms + l4]);
        float inv1 = 1.0f / (ps[ms + l4 + 8] + ps[64 + ms + l4 + 8]);
        #pragma unroll
        for (int jc = 0; jc < 4; ++jc)
            #pragma unroll
            for (int q = 0; q < 2; ++q) {
                int row = ms + l4 + q * 8;
                int j0  = ns + jc * 8 + l2 * 2;
                float inv = q ? inv1 : inv0;
                float p0 = s[jc][q * 2] * inv, p1 = s[jc][q * 2 + 1] * inv;
                __half h0 = __float2half(p0), h1 = __float2half(p1);
                __half lo0 = __float2half(p0 - __half2float(h0));
                __half lo1 = __float2half(p1 - __half2float(h1));
                uint32_t off = l128(row, j0 >> 3) + (j0 & 7) * 2;
                *(__half2*)(am_raw + AT_P  + off) = __halves2half2(h0, h1);
                *(__half2*)(am_raw + AT_PL + off) = __halves2half2(lo0, lo1);
            }
    }
    __syncthreads();

    // ---- Wh/Ww masked row sums -> WW tile ----
    {
        int r = tid & 15, it0 = tid >> 4;
        for (int i = it0; i < 64; i += 16) {
            float wh = 0.f, ww = 0.f;
            if (r < 15) {
                int rowj = (i >> 3) - (r - 7);
                if (rowj >= 0 && rowj < 8) {
                    const __half* hp = (const __half*)(am_raw + AT_P  + l128(i, rowj));
                    const __half* lp = (const __half*)(am_raw + AT_PL + l128(i, rowj));
                    #pragma unroll
                    for (int t = 0; t < 8; ++t)
                        wh += __half2float(hp[t]) + __half2float(lp[t]);
                }
                int colj = (i & 7) - (r - 7);
                if (colj >= 0 && colj < 8) {
                    #pragma unroll
                    for (int rj = 0; rj < 8; ++rj) {
                        ww += __half2float(*(const __half*)(am_raw + AT_P  + l128(i, rj) + colj * 2))
                            + __half2float(*(const __half*)(am_raw + AT_PL + l128(i, rj) + colj * 2));
                    }
                }
            }
            __half hwh = __float2half(wh), hww = __float2half(ww);
            int cw = r + 16;
            *(unsigned short*)(am_raw + AT_WW + l64(i, r >> 3)  + (r  & 7) * 2) = *(unsigned short*)&hwh;
            *(unsigned short*)(am_raw + AT_WW + l64(i, cw >> 3) + (cw & 7) * 2) = *(unsigned short*)&hww;
        }
    }
    __syncthreads();

    // ---- ctx: P·V (trans-B, 2-term) + WW·EC (trans-B) ----
    {
        float o[4][4];
        #pragma unroll
        for (int j = 0; j < 4; ++j) { o[j][0]=o[j][1]=o[j][2]=o[j][3]=0.f; }
        int trow = (lane & 7) + ((lane >> 3) & 1) * 8;
        int tsel = lane >> 4;

        #pragma unroll
        for (int kk = 0; kk < 4; ++kk) {
            int c = 2 * kk + lc;
            uint32_t ph[4], pl[4];
            uint32_t offp = l128(ms + lrow, c);
            ldsm4(ph, sb + AT_P  + offp);
            ldsm4(pl, sb + AT_PL + offp);
            #pragma unroll
            for (int jp = 0; jp < 2; ++jp) {
                uint32_t bv[4];
                ldsm4t(bv, sb + AT_V + l128(kk * 16 + trow, (ns >> 3) + jp * 2 + tsel));
                mma16816(o[jp * 2],     ph, bv[0], bv[1]);
                mma16816(o[jp * 2],     pl, bv[0], bv[1]);
                mma16816(o[jp * 2 + 1], ph, bv[2], bv[3]);
                mma16816(o[jp * 2 + 1], pl, bv[2], bv[3]);
            }
        }
        #pragma unroll
        for (int kk2 = 0; kk2 < 2; ++kk2) {
            uint32_t aw_[4];
            ldsm4(aw_, sb + AT_WW + l64(ms + lrow, 2 * kk2 + lc));
            #pragma unroll
            for (int jp = 0; jp < 2; ++jp) {
                uint32_t ev[4];
                ldsm4t(ev, sb + AT_EC + l128(kk2 * 16 + trow, (ns >> 3) + jp * 2 + tsel));
                mma16816(o[jp * 2],     aw_, ev[0], ev[1]);
                mma16816(o[jp * 2 + 1], aw_, ev[2], ev[3]);
            }
        }
        #pragma unroll
        for (int jc = 0; jc < 4; ++jc) {
            int d = ns + jc * 8 + l2 * 2;
            int i = ms + l4;
            *(__half2*)(g_a + (size_t)(b * 64 + i) * DD + h * 64 + d) =
                __halves2half2(__float2half(o[jc][0]), __float2half(o[jc][1]));
            *(__half2*)(g_a + (size_t)(b * 64 + i + 8) * DD + h * 64 + d) =
                __halves2half2(__float2half(o[jc][2]), __float2half(o[jc][3]));
        }
    }
}

// ---------------------------------------------------------------------------
extern "C" void kernel_launch(void* const* d_in, const int* in_sizes, int n_in,
                              void* d_out, int out_size) {
    const float* x    = (const float*)d_in[0];
    const float* wq   = (const float*)d_in[1];
    const float* wk   = (const float*)d_in[2];
    const float* wv   = (const float*)d_in[3];
    const float* wo   = (const float*)d_in[4];
    const float* bo   = (const float*)d_in[5];
    const float* eq_h = (const float*)d_in[6];
    const float* eq_w = (const float*)d_in[7];
    const float* ek_h = (const float*)d_in[8];
    const float* ek_w = (const float*)d_in[9];
    const float* ev_h = (const float*)d_in[10];
    const float* ev_w = (const float*)d_in[11];
    float* out = (float*)d_out;

    cudaFuncSetAttribute(qkv_hmma, cudaFuncAttributeMaxDynamicSharedMemorySize, GEMM_SMEM);
    cudaFuncSetAttribute(out_hmma, cudaFuncAttributeMaxDynamicSharedMemorySize, GEMM_SMEM);
    cudaFuncSetAttribute(attn_mma, cudaFuncAttributeMaxDynamicSharedMemorySize, AT_BYTES);

    mega_prep<<<6184, 256>>>(x, wq, wk, wv, wo, eq_h, eq_w, ek_h, ek_w, ev_h, ev_w);
    qkv_hmma<<<dim3(24, 128), 512, GEMM_SMEM>>>();
    attn_mma<<<BB * HH, 256, AT_BYTES>>>();
    out_hmma<<<dim3(8, 128), 512, GEMM_SMEM>>>(bo, out);
}